// round 5
// baseline (speedup 1.0000x reference)
#include <cuda_runtime.h>

#define NMAX 100000
#define EMAX 1600000
#define HIDD 64
#define FIN  128

// Scratch (allocation-free rule: __device__ globals)
__device__ int   g_cnt[NMAX];
__device__ int   g_off[NMAX + 1];
__device__ int   g_cur[NMAX];
__device__ int   g_esrc[EMAX];
__device__ int   g_bsum[512];
__device__ float g_dinv[NMAX];
__device__ float g_hl[NMAX * HIDD];
__device__ float g_h [NMAX * HIDD];
__device__ float g_ab[NMAX * 2 * HIDD];
__device__ float g_wab[HIDD * 2 * HIDD];

// side stream + events for fork-join capture (created once; no device memory)
static cudaStream_t g_s2;
static cudaEvent_t g_evFork, g_evJoin;
namespace { struct StreamInit {
    StreamInit() {
        cudaStreamCreateWithFlags(&g_s2, cudaStreamNonBlocking);
        cudaEventCreateWithFlags(&g_evFork, cudaEventDisableTiming);
        cudaEventCreateWithFlags(&g_evJoin, cudaEventDisableTiming);
    }
} g_streamInit; }

// ---------------- CSC build ----------------
__global__ void zero_cnt(int* __restrict__ cnt, int n) {
    int i = blockIdx.x * blockDim.x + threadIdx.x;
    if (i < n) cnt[i] = 0;
}

__global__ void count_in(const int* __restrict__ col, int* __restrict__ cnt, int E) {
    int e = blockIdx.x * blockDim.x + threadIdx.x;
    if (e < E) atomicAdd(&cnt[col[e]], 1);
}

// exclusive scan within block + block totals + dinv = rsqrt(cnt+1)
__global__ void scan1(const int* __restrict__ cnt, int* __restrict__ off,
                      int* __restrict__ bsum, float* __restrict__ dinv, int n) {
    __shared__ int s[256];
    int tid = threadIdx.x;
    int i = blockIdx.x * 256 + tid;
    int v = (i < n) ? cnt[i] : 0;
    if (i < n) dinv[i] = rsqrtf((float)v + 1.0f);
    s[tid] = v;
    __syncthreads();
#pragma unroll
    for (int d = 1; d < 256; d <<= 1) {
        int t = (tid >= d) ? s[tid - d] : 0;
        __syncthreads();
        s[tid] += t;
        __syncthreads();
    }
    if (i < n) off[i] = s[tid] - v;
    if (tid == 255) bsum[blockIdx.x] = s[255];
}

__global__ void scan2(int* __restrict__ bsum, int nb) {
    __shared__ int s[512];
    int tid = threadIdx.x;
    int v = (tid < nb) ? bsum[tid] : 0;
    s[tid] = v;
    __syncthreads();
#pragma unroll
    for (int d = 1; d < 512; d <<= 1) {
        int t = (tid >= d) ? s[tid - d] : 0;
        __syncthreads();
        s[tid] += t;
        __syncthreads();
    }
    if (tid < nb) bsum[tid] = s[tid] - v;
}

__global__ void scan3(int* __restrict__ off, const int* __restrict__ bsum,
                      int* __restrict__ cur, int n, int E) {
    int i = blockIdx.x * 256 + threadIdx.x;
    if (i < n) {
        int o = off[i] + bsum[blockIdx.x];
        off[i] = o;
        cur[i] = o;
    }
    if (i == 0) off[n] = E;
}

__global__ void fill_csr(const int* __restrict__ row, const int* __restrict__ col,
                         int* __restrict__ cur, int* __restrict__ esrc, int E) {
    int e = blockIdx.x * blockDim.x + threadIdx.x;
    if (e < E) {
        int p = atomicAdd(&cur[col[e]], 1);
        esrc[p] = row[e];
    }
}

// ---------------- GEMM: Y[r,:] = (X[r,:] @ W) * (dinv ? dinv[r] : 1) ----------------
// 256 threads; 8 rows x 4 cols per thread; K chunked at 32.
template <int K, int N>
__global__ void gemm_tiled(const float* __restrict__ X, const float* __restrict__ W,
                           const float* __restrict__ dinv, float* __restrict__ Y, int nrows) {
    constexpr int CG = N / 4;            // 16 (N=64) or 32 (N=128)
    constexpr int TR = 8;
    constexpr int RQ = 256 / CG;         // 16 or 8
    constexpr int ROWS = RQ * TR;        // 128 or 64
    constexpr int KC = 32;
    constexpr int NCH = K / KC;
    constexpr int XP = KC + 4;
    __shared__ float Xs[ROWS][XP];
    __shared__ float Ws[KC][N];
    int tid = threadIdx.x;
    int row0 = blockIdx.x * ROWS;
    int cg = tid % CG, rq = tid / CG;
    float acc[TR][4] = {};

    for (int ch = 0; ch < NCH; ch++) {
        int k0 = ch * KC;
#pragma unroll
        for (int j = tid; j < ROWS * (KC / 4); j += 256) {
            int r = j / (KC / 4), kq = j % (KC / 4);
            int gr = row0 + r;
            float4 v = (gr < nrows)
                ? *reinterpret_cast<const float4*>(&X[(size_t)gr * K + k0 + kq * 4])
                : make_float4(0.f, 0.f, 0.f, 0.f);
            *reinterpret_cast<float4*>(&Xs[r][kq * 4]) = v;
        }
#pragma unroll
        for (int j = tid; j < KC * (N / 4); j += 256) {
            int k = j / (N / 4), nq = j % (N / 4);
            *reinterpret_cast<float4*>(&Ws[k][nq * 4]) =
                *reinterpret_cast<const float4*>(&W[(size_t)(k0 + k) * N + nq * 4]);
        }
        __syncthreads();
#pragma unroll
        for (int k = 0; k < KC; k++) {
            float4 w = *reinterpret_cast<const float4*>(&Ws[k][cg * 4]);
#pragma unroll
            for (int i = 0; i < TR; i++) {
                float xv = Xs[rq * TR + i][k];
                acc[i][0] += xv * w.x;
                acc[i][1] += xv * w.y;
                acc[i][2] += xv * w.z;
                acc[i][3] += xv * w.w;
            }
        }
        __syncthreads();
    }
#pragma unroll
    for (int i = 0; i < TR; i++) {
        int gr = row0 + rq * TR + i;
        if (gr < nrows) {
            float s = dinv ? dinv[gr] : 1.0f;
            float4 o = make_float4(acc[i][0] * s, acc[i][1] * s, acc[i][2] * s, acc[i][3] * s);
            *reinterpret_cast<float4*>(&Y[(size_t)gr * N + cg * 4]) = o;
        }
    }
}

// ---------------- aggregation ----------------
// SCALE_SRC=true : hls unscaled -> acc = dinv[c]*hls[c] + sum dinv[src]*hls[src]
// SCALE_SRC=false: hls pre-scaled by dinv[src] -> acc = hls[c] + sum hls[src]
// out: h[c] = relu(acc * dinv[c] + b)
template <bool SCALE_SRC>
__global__ void gather_agg(const int* __restrict__ off, const int* __restrict__ esrc,
                           const float* __restrict__ hls, const float* __restrict__ dinv,
                           const float* __restrict__ bias, float* __restrict__ h, int n) {
    __shared__ float sb[64];
    if (threadIdx.x < 64) sb[threadIdx.x] = bias[threadIdx.x];
    __syncthreads();
    int gid = blockIdx.x * 256 + threadIdx.x;
    int c = gid >> 4;
    if (c >= n) return;
    int l = gid & 15;
    const float4* hp = reinterpret_cast<const float4*>(hls);
    float dc = dinv[c];
    float4 acc = hp[(size_t)c * 16 + l];
    if (SCALE_SRC) { acc.x *= dc; acc.y *= dc; acc.z *= dc; acc.w *= dc; }
    int s = off[c], e2 = off[c + 1];
    int j = s;
    for (; j + 1 < e2; j += 2) {
        int r0 = esrc[j], r1 = esrc[j + 1];
        float4 v0 = hp[(size_t)r0 * 16 + l];
        float4 v1 = hp[(size_t)r1 * 16 + l];
        if (SCALE_SRC) {
            float w0 = dinv[r0], w1 = dinv[r1];
            acc.x += v0.x * w0 + v1.x * w1; acc.y += v0.y * w0 + v1.y * w1;
            acc.z += v0.z * w0 + v1.z * w1; acc.w += v0.w * w0 + v1.w * w1;
        } else {
            acc.x += v0.x + v1.x; acc.y += v0.y + v1.y;
            acc.z += v0.z + v1.z; acc.w += v0.w + v1.w;
        }
    }
    if (j < e2) {
        int r = esrc[j];
        float4 v = hp[(size_t)r * 16 + l];
        if (SCALE_SRC) {
            float w = dinv[r];
            acc.x += v.x * w; acc.y += v.y * w; acc.z += v.z * w; acc.w += v.w * w;
        } else {
            acc.x += v.x; acc.y += v.y; acc.z += v.z; acc.w += v.w;
        }
    }
    int jb = l * 4;
    float4 o;
    o.x = fmaxf(acc.x * dc + sb[jb + 0], 0.f);
    o.y = fmaxf(acc.y * dc + sb[jb + 1], 0.f);
    o.z = fmaxf(acc.z * dc + sb[jb + 2], 0.f);
    o.w = fmaxf(acc.w * dc + sb[jb + 3], 0.f);
    reinterpret_cast<float4*>(h)[(size_t)c * 16 + l] = o;
}

__global__ void repack_wab(const float* __restrict__ l1W, float* __restrict__ wab) {
    int i = blockIdx.x * blockDim.x + threadIdx.x;
    if (i < 64 * 128) {
        int k = i >> 7, nn = i & 127;
        wab[i] = (nn < 64) ? l1W[k * 64 + nn] : l1W[(64 + k) * 64 + (nn - 64)];
    }
}

__global__ void edge_mlp(const int* __restrict__ row, const int* __restrict__ col,
                         const float* __restrict__ ab, const float* __restrict__ l1b,
                         const float* __restrict__ l2w, const float* __restrict__ l2b,
                         float* __restrict__ out, int E) {
    __shared__ float s1b[64], s2w[128], s2b[2];
    int tid = threadIdx.x;
    if (tid < 64)        s1b[tid]       = l1b[tid];
    else if (tid < 192)  s2w[tid - 64]  = l2w[tid - 64];
    else if (tid < 194)  s2b[tid - 192] = l2b[tid - 192];
    __syncthreads();
    int gid = blockIdx.x * 256 + tid;
    int e = gid >> 4;
    if (e >= E) return;
    int l = gid & 15;
    int r = row[e], c = col[e];
    float4 a = *reinterpret_cast<const float4*>(&ab[(size_t)r * 128 + l * 4]);
    float4 b = *reinterpret_cast<const float4*>(&ab[(size_t)c * 128 + 64 + l * 4]);
    int j = l * 4;
    float s0 = 0.f, s1 = 0.f, z;
    z = fmaxf(a.x + b.x + s1b[j + 0], 0.f); s0 += z * s2w[(j + 0) * 2]; s1 += z * s2w[(j + 0) * 2 + 1];
    z = fmaxf(a.y + b.y + s1b[j + 1], 0.f); s0 += z * s2w[(j + 1) * 2]; s1 += z * s2w[(j + 1) * 2 + 1];
    z = fmaxf(a.z + b.z + s1b[j + 2], 0.f); s0 += z * s2w[(j + 2) * 2]; s1 += z * s2w[(j + 2) * 2 + 1];
    z = fmaxf(a.w + b.w + s1b[j + 3], 0.f); s0 += z * s2w[(j + 3) * 2]; s1 += z * s2w[(j + 3) * 2 + 1];
#pragma unroll
    for (int off = 8; off > 0; off >>= 1) {
        s0 += __shfl_down_sync(0xFFFFFFFFu, s0, off, 16);
        s1 += __shfl_down_sync(0xFFFFFFFFu, s1, off, 16);
    }
    if (l == 0) {
        s0 += s2b[0]; s1 += s2b[1];
        float m = fmaxf(s0, s1);
        float lse = m + logf(expf(s0 - m) + expf(s1 - m));
        float2 o = make_float2(s0 - lse, s1 - lse);
        *reinterpret_cast<float2*>(&out[2 * (size_t)e]) = o;
    }
}

extern "C" void kernel_launch(void* const* d_in, const int* in_sizes, int n_in,
                              void* d_out, int out_size) {
    const float* x   = (const float*)d_in[0];
    const int*   ei  = (const int*)d_in[1];
    const float* W1  = (const float*)d_in[2];
    const float* b1  = (const float*)d_in[3];
    const float* W2  = (const float*)d_in[4];
    const float* b2  = (const float*)d_in[5];
    const float* l1W = (const float*)d_in[6];
    const float* l1b = (const float*)d_in[7];
    const float* l2W = (const float*)d_in[8];
    const float* l2b = (const float*)d_in[9];
    float* out = (float*)d_out;

    int n = in_sizes[0] / FIN;
    int E = in_sizes[1] / 2;
    const int* row = ei;
    const int* col = ei + E;

    int *cnt, *off, *cur, *esrc, *bsum;
    float *dinv, *hl, *h, *ab, *wab;
    cudaGetSymbolAddress((void**)&cnt,  g_cnt);
    cudaGetSymbolAddress((void**)&off,  g_off);
    cudaGetSymbolAddress((void**)&cur,  g_cur);
    cudaGetSymbolAddress((void**)&esrc, g_esrc);
    cudaGetSymbolAddress((void**)&bsum, g_bsum);
    cudaGetSymbolAddress((void**)&dinv, g_dinv);
    cudaGetSymbolAddress((void**)&hl,   g_hl);
    cudaGetSymbolAddress((void**)&h,    g_h);
    cudaGetSymbolAddress((void**)&ab,   g_ab);
    cudaGetSymbolAddress((void**)&wab,  g_wab);

    const int T = 256;
    int NB = (n + 255) / 256;

    // fork: CSR build + repack on side stream, gemm1 on main
    zero_cnt<<<NB, T>>>(cnt, n);
    cudaEventRecord(g_evFork, 0);
    cudaStreamWaitEvent(g_s2, g_evFork, 0);
    count_in<<<(E + T - 1) / T, T, 0, g_s2>>>(col, cnt, E);
    scan1<<<NB, T, 0, g_s2>>>(cnt, off, bsum, dinv, n);
    scan2<<<1, 512, 0, g_s2>>>(bsum, NB);
    scan3<<<NB, T, 0, g_s2>>>(off, bsum, cur, n, E);
    fill_csr<<<(E + T - 1) / T, T, 0, g_s2>>>(row, col, cur, esrc, E);
    repack_wab<<<(64 * 128 + T - 1) / T, T, 0, g_s2>>>(l1W, wab);
    cudaEventRecord(g_evJoin, g_s2);

    // gemm1 overlaps the CSR chain (writes UNscaled hl)
    gemm_tiled<128, 64><<<(n + 127) / 128, 256>>>(x, W1, (const float*)nullptr, hl, n);
    cudaStreamWaitEvent(0, g_evJoin, 0);

    // layer 1: per-edge dinv scaling in gather
    gather_agg<true><<<(n * 16 + T - 1) / T, T>>>(off, esrc, hl, dinv, b1, h, n);

    // layer 2: pre-scaled in gemm epilogue
    gemm_tiled<64, 64><<<(n + 127) / 128, 256>>>(h, W2, dinv, hl, n);
    gather_agg<false><<<(n * 16 + T - 1) / T, T>>>(off, esrc, hl, dinv, b2, h, n);

    // edge MLP
    gemm_tiled<64, 128><<<(n + 63) / 64, 256>>>(h, wab, (const float*)nullptr, ab, n);
    edge_mlp<<<(E * 16 + T - 1) / T, T>>>(row, col, ab, l1b, l2W, l2b, out, E);
}

// round 6
// speedup vs baseline: 1.0277x; 1.0277x over previous
#include <cuda_runtime.h>

#define NMAX 100000
#define EMAX 1600000
#define HIDD 64
#define FIN  128

__device__ int   g_cnt[NMAX];
__device__ int   g_off[NMAX + 1];
__device__ int   g_cur[NMAX];
__device__ int   g_esrc[EMAX];
__device__ int   g_bsum[512];
__device__ float g_dinv[NMAX];
__device__ float g_hl[NMAX * HIDD];
__device__ float g_h [NMAX * HIDD];
__device__ float g_ab[NMAX * 2 * HIDD];
__device__ float g_wab[HIDD * 2 * HIDD];

// side stream + events for fork-join capture (no device memory involved)
static cudaStream_t g_s2;
static cudaEvent_t g_evFork, g_evJoin;
namespace { struct StreamInit {
    StreamInit() {
        cudaStreamCreateWithFlags(&g_s2, cudaStreamNonBlocking);
        cudaEventCreateWithFlags(&g_evFork, cudaEventDisableTiming);
        cudaEventCreateWithFlags(&g_evJoin, cudaEventDisableTiming);
    }
} g_streamInit; }

// ---------------- CSC build ----------------
__global__ void zero_cnt(int* __restrict__ cnt, int n) {
    int i = blockIdx.x * blockDim.x + threadIdx.x;
    if (i < n) cnt[i] = 0;
}

__global__ void count_in(const int* __restrict__ col, int* __restrict__ cnt, int E) {
    int e = blockIdx.x * blockDim.x + threadIdx.x;
    if (e < E) atomicAdd(&cnt[col[e]], 1);
}

// exclusive scan within block + block totals + dinv = rsqrt(cnt+1)
__global__ void scan1(const int* __restrict__ cnt, int* __restrict__ off,
                      int* __restrict__ bsum, float* __restrict__ dinv, int n) {
    __shared__ int s[256];
    int tid = threadIdx.x;
    int i = blockIdx.x * 256 + tid;
    int v = (i < n) ? cnt[i] : 0;
    if (i < n) dinv[i] = rsqrtf((float)v + 1.0f);
    s[tid] = v;
    __syncthreads();
#pragma unroll
    for (int d = 1; d < 256; d <<= 1) {
        int t = (tid >= d) ? s[tid - d] : 0;
        __syncthreads();
        s[tid] += t;
        __syncthreads();
    }
    if (i < n) off[i] = s[tid] - v;
    if (tid == 255) bsum[blockIdx.x] = s[255];
}

__global__ void scan2(int* __restrict__ bsum, int nb) {
    __shared__ int s[512];
    int tid = threadIdx.x;
    int v = (tid < nb) ? bsum[tid] : 0;
    s[tid] = v;
    __syncthreads();
#pragma unroll
    for (int d = 1; d < 512; d <<= 1) {
        int t = (tid >= d) ? s[tid - d] : 0;
        __syncthreads();
        s[tid] += t;
        __syncthreads();
    }
    if (tid < nb) bsum[tid] = s[tid] - v;
}

__global__ void scan3(int* __restrict__ off, const int* __restrict__ bsum,
                      int* __restrict__ cur, int n, int E) {
    int i = blockIdx.x * 256 + threadIdx.x;
    if (i < n) {
        int o = off[i] + bsum[blockIdx.x];
        off[i] = o;
        cur[i] = o;
    }
    if (i == 0) off[n] = E;
}

__global__ void fill_csr(const int* __restrict__ row, const int* __restrict__ col,
                         int* __restrict__ cur, int* __restrict__ esrc, int E) {
    int e = blockIdx.x * blockDim.x + threadIdx.x;
    if (e < E) {
        int p = atomicAdd(&cur[col[e]], 1);
        esrc[p] = row[e];
    }
}

// ---------------- GEMM (R4 config: 4 rows x 4 cols per thread, KC=64) ----------------
template <int K, int N>
__global__ void gemm_tiled(const float* __restrict__ X, const float* __restrict__ W,
                           const float* __restrict__ dinv, float* __restrict__ Y, int nrows) {
    constexpr int CG = N / 4;
    constexpr int TR = 4;
    constexpr int RQ = 256 / CG;
    constexpr int ROWS = RQ * TR;       // 64 (N=64) or 32 (N=128)
    constexpr int KC = 64;
    constexpr int NCH = K / KC;
    constexpr int XP = KC + 4;
    __shared__ float Xs[ROWS][XP];
    __shared__ float Ws[KC][N];
    int tid = threadIdx.x;
    int row0 = blockIdx.x * ROWS;
    int cg = tid % CG, rq = tid / CG;
    float acc[TR][4] = {};

    for (int ch = 0; ch < NCH; ch++) {
        int k0 = ch * KC;
        for (int j = tid; j < ROWS * (KC / 4); j += 256) {
            int r = j / (KC / 4), kq = j % (KC / 4);
            int gr = row0 + r;
            float4 v = (gr < nrows)
                ? *reinterpret_cast<const float4*>(&X[(size_t)gr * K + k0 + kq * 4])
                : make_float4(0.f, 0.f, 0.f, 0.f);
            *reinterpret_cast<float4*>(&Xs[r][kq * 4]) = v;
        }
        for (int j = tid; j < KC * (N / 4); j += 256) {
            int k = j / (N / 4), nq = j % (N / 4);
            *reinterpret_cast<float4*>(&Ws[k][nq * 4]) =
                *reinterpret_cast<const float4*>(&W[(size_t)(k0 + k) * N + nq * 4]);
        }
        __syncthreads();
#pragma unroll
        for (int k = 0; k < KC; k++) {
            float4 w = *reinterpret_cast<const float4*>(&Ws[k][cg * 4]);
#pragma unroll
            for (int i = 0; i < TR; i++) {
                float xv = Xs[rq * TR + i][k];
                acc[i][0] += xv * w.x;
                acc[i][1] += xv * w.y;
                acc[i][2] += xv * w.z;
                acc[i][3] += xv * w.w;
            }
        }
        __syncthreads();
    }
#pragma unroll
    for (int i = 0; i < TR; i++) {
        int gr = row0 + rq * TR + i;
        if (gr < nrows) {
            float s = dinv ? dinv[gr] : 1.0f;
            float4 o = make_float4(acc[i][0] * s, acc[i][1] * s, acc[i][2] * s, acc[i][3] * s);
            *reinterpret_cast<float4*>(&Y[(size_t)gr * N + cg * 4]) = o;
        }
    }
}

// ---------------- aggregation ----------------
template <bool SCALE_SRC>
__global__ void gather_agg(const int* __restrict__ off, const int* __restrict__ esrc,
                           const float* __restrict__ hls, const float* __restrict__ dinv,
                           const float* __restrict__ bias, float* __restrict__ h, int n) {
    __shared__ float sb[64];
    if (threadIdx.x < 64) sb[threadIdx.x] = bias[threadIdx.x];
    __syncthreads();
    int gid = blockIdx.x * 256 + threadIdx.x;
    int c = gid >> 4;
    if (c >= n) return;
    int l = gid & 15;
    const float4* hp = reinterpret_cast<const float4*>(hls);
    float dc = dinv[c];
    float4 acc = hp[(size_t)c * 16 + l];
    if (SCALE_SRC) { acc.x *= dc; acc.y *= dc; acc.z *= dc; acc.w *= dc; }
    int s = off[c], e2 = off[c + 1];
    int j = s;
    for (; j + 1 < e2; j += 2) {
        int r0 = esrc[j], r1 = esrc[j + 1];
        float4 v0 = hp[(size_t)r0 * 16 + l];
        float4 v1 = hp[(size_t)r1 * 16 + l];
        if (SCALE_SRC) {
            float w0 = dinv[r0], w1 = dinv[r1];
            acc.x += v0.x * w0 + v1.x * w1; acc.y += v0.y * w0 + v1.y * w1;
            acc.z += v0.z * w0 + v1.z * w1; acc.w += v0.w * w0 + v1.w * w1;
        } else {
            acc.x += v0.x + v1.x; acc.y += v0.y + v1.y;
            acc.z += v0.z + v1.z; acc.w += v0.w + v1.w;
        }
    }
    if (j < e2) {
        int r = esrc[j];
        float4 v = hp[(size_t)r * 16 + l];
        if (SCALE_SRC) {
            float w = dinv[r];
            acc.x += v.x * w; acc.y += v.y * w; acc.z += v.z * w; acc.w += v.w * w;
        } else {
            acc.x += v.x; acc.y += v.y; acc.z += v.z; acc.w += v.w;
        }
    }
    int jb = l * 4;
    float4 o;
    o.x = fmaxf(acc.x * dc + sb[jb + 0], 0.f);
    o.y = fmaxf(acc.y * dc + sb[jb + 1], 0.f);
    o.z = fmaxf(acc.z * dc + sb[jb + 2], 0.f);
    o.w = fmaxf(acc.w * dc + sb[jb + 3], 0.f);
    reinterpret_cast<float4*>(h)[(size_t)c * 16 + l] = o;
}

__global__ void repack_wab(const float* __restrict__ l1W, float* __restrict__ wab) {
    int i = blockIdx.x * blockDim.x + threadIdx.x;
    if (i < 64 * 128) {
        int k = i >> 7, nn = i & 127;
        wab[i] = (nn < 64) ? l1W[k * 64 + nn] : l1W[(64 + k) * 64 + (nn - 64)];
    }
}

__global__ void edge_mlp(const int* __restrict__ row, const int* __restrict__ col,
                         const float* __restrict__ ab, const float* __restrict__ l1b,
                         const float* __restrict__ l2w, const float* __restrict__ l2b,
                         float* __restrict__ out, int E) {
    __shared__ float s1b[64], s2w[128], s2b[2];
    int tid = threadIdx.x;
    if (tid < 64)        s1b[tid]       = l1b[tid];
    else if (tid < 192)  s2w[tid - 64]  = l2w[tid - 64];
    else if (tid < 194)  s2b[tid - 192] = l2b[tid - 192];
    __syncthreads();
    int gid = blockIdx.x * 256 + tid;
    int e = gid >> 4;
    if (e >= E) return;
    int l = gid & 15;
    int r = row[e], c = col[e];
    float4 a = *reinterpret_cast<const float4*>(&ab[(size_t)r * 128 + l * 4]);
    float4 b = *reinterpret_cast<const float4*>(&ab[(size_t)c * 128 + 64 + l * 4]);
    int j = l * 4;
    float s0 = 0.f, s1 = 0.f, z;
    z = fmaxf(a.x + b.x + s1b[j + 0], 0.f); s0 += z * s2w[(j + 0) * 2]; s1 += z * s2w[(j + 0) * 2 + 1];
    z = fmaxf(a.y + b.y + s1b[j + 1], 0.f); s0 += z * s2w[(j + 1) * 2]; s1 += z * s2w[(j + 1) * 2 + 1];
    z = fmaxf(a.z + b.z + s1b[j + 2], 0.f); s0 += z * s2w[(j + 2) * 2]; s1 += z * s2w[(j + 2) * 2 + 1];
    z = fmaxf(a.w + b.w + s1b[j + 3], 0.f); s0 += z * s2w[(j + 3) * 2]; s1 += z * s2w[(j + 3) * 2 + 1];
#pragma unroll
    for (int off = 8; off > 0; off >>= 1) {
        s0 += __shfl_down_sync(0xFFFFFFFFu, s0, off, 16);
        s1 += __shfl_down_sync(0xFFFFFFFFu, s1, off, 16);
    }
    if (l == 0) {
        s0 += s2b[0]; s1 += s2b[1];
        float m = fmaxf(s0, s1);
        float lse = m + logf(expf(s0 - m) + expf(s1 - m));
        float2 o = make_float2(s0 - lse, s1 - lse);
        *reinterpret_cast<float2*>(&out[2 * (size_t)e]) = o;
    }
}

extern "C" void kernel_launch(void* const* d_in, const int* in_sizes, int n_in,
                              void* d_out, int out_size) {
    const float* x   = (const float*)d_in[0];
    const int*   ei  = (const int*)d_in[1];
    const float* W1  = (const float*)d_in[2];
    const float* b1  = (const float*)d_in[3];
    const float* W2  = (const float*)d_in[4];
    const float* b2  = (const float*)d_in[5];
    const float* l1W = (const float*)d_in[6];
    const float* l1b = (const float*)d_in[7];
    const float* l2W = (const float*)d_in[8];
    const float* l2b = (const float*)d_in[9];
    float* out = (float*)d_out;

    int n = in_sizes[0] / FIN;
    int E = in_sizes[1] / 2;
    const int* row = ei;
    const int* col = ei + E;

    int *cnt, *off, *cur, *esrc, *bsum;
    float *dinv, *hl, *h, *ab, *wab;
    cudaGetSymbolAddress((void**)&cnt,  g_cnt);
    cudaGetSymbolAddress((void**)&off,  g_off);
    cudaGetSymbolAddress((void**)&cur,  g_cur);
    cudaGetSymbolAddress((void**)&esrc, g_esrc);
    cudaGetSymbolAddress((void**)&bsum, g_bsum);
    cudaGetSymbolAddress((void**)&dinv, g_dinv);
    cudaGetSymbolAddress((void**)&hl,   g_hl);
    cudaGetSymbolAddress((void**)&h,    g_h);
    cudaGetSymbolAddress((void**)&ab,   g_ab);
    cudaGetSymbolAddress((void**)&wab,  g_wab);

    const int T = 256;
    int NB = (n + 255) / 256;

    // fork: CSR build + repack on side stream; gemm1 on main
    zero_cnt<<<NB, T>>>(cnt, n);
    cudaEventRecord(g_evFork, 0);
    cudaStreamWaitEvent(g_s2, g_evFork, 0);
    count_in<<<(E + T - 1) / T, T, 0, g_s2>>>(col, cnt, E);
    scan1<<<NB, T, 0, g_s2>>>(cnt, off, bsum, dinv, n);
    scan2<<<1, 512, 0, g_s2>>>(bsum, NB);
    scan3<<<NB, T, 0, g_s2>>>(off, bsum, cur, n, E);
    fill_csr<<<(E + T - 1) / T, T, 0, g_s2>>>(row, col, cur, esrc, E);
    repack_wab<<<(64 * 128 + T - 1) / T, T, 0, g_s2>>>(l1W, wab);
    cudaEventRecord(g_evJoin, g_s2);

    // gemm1 overlaps CSR chain (writes UNscaled hl)
    gemm_tiled<128, 64><<<(n + 63) / 64, 256>>>(x, W1, (const float*)nullptr, hl, n);
    cudaStreamWaitEvent(0, g_evJoin, 0);

    // layer 1: per-edge dinv scaling in gather
    gather_agg<true><<<(n * 16 + T - 1) / T, T>>>(off, esrc, hl, dinv, b1, h, n);

    // layer 2: pre-scaled in gemm epilogue
    gemm_tiled<64, 64><<<(n + 63) / 64, 256>>>(h, W2, dinv, hl, n);
    gather_agg<false><<<(n * 16 + T - 1) / T, T>>>(off, esrc, hl, dinv, b2, h, n);

    // edge MLP
    gemm_tiled<64, 128><<<(n + 31) / 32, 256>>>(h, wab, (const float*)nullptr, ab, n);
    edge_mlp<<<(E * 16 + T - 1) / T, T>>>(row, col, ab, l1b, l2W, l2b, out, E);
}

// round 7
// speedup vs baseline: 1.0851x; 1.0558x over previous
#include <cuda_runtime.h>
#include <cuda_fp16.h>

#define NMAX 100000
#define EMAX 1600000
#define HIDD 64
#define FIN  128

__device__ int     g_cnt[NMAX];
__device__ int     g_off[NMAX + 1];
__device__ int     g_cur[NMAX];
__device__ int     g_esrc[EMAX];
__device__ int     g_bsum[512];
__device__ float   g_dinv[NMAX];
__device__ __half2 g_hl2[NMAX * HIDD / 2];      // fp16 linear features (gather input)
__device__ float   g_h [NMAX * HIDD];           // aggregated features (fp32)
__device__ __half2 g_ab2[NMAX * HIDD];          // fp16 [A|B] table (edge_mlp input)
__device__ float   g_wab[HIDD * 2 * HIDD];

static cudaStream_t g_s2;
static cudaEvent_t g_evFork, g_evJoin;
namespace { struct StreamInit {
    StreamInit() {
        cudaStreamCreateWithFlags(&g_s2, cudaStreamNonBlocking);
        cudaEventCreateWithFlags(&g_evFork, cudaEventDisableTiming);
        cudaEventCreateWithFlags(&g_evJoin, cudaEventDisableTiming);
    }
} g_streamInit; }

// ---------------- CSC build ----------------
__global__ void zero_cnt(int* __restrict__ cnt, int n) {
    int i = blockIdx.x * blockDim.x + threadIdx.x;
    if (i < n) cnt[i] = 0;
}

__global__ void count_in(const int* __restrict__ col, int* __restrict__ cnt, int E) {
    int e = blockIdx.x * blockDim.x + threadIdx.x;
    if (e < E) atomicAdd(&cnt[col[e]], 1);
}

__global__ void scan1(const int* __restrict__ cnt, int* __restrict__ off,
                      int* __restrict__ bsum, float* __restrict__ dinv, int n) {
    __shared__ int s[256];
    int tid = threadIdx.x;
    int i = blockIdx.x * 256 + tid;
    int v = (i < n) ? cnt[i] : 0;
    if (i < n) dinv[i] = rsqrtf((float)v + 1.0f);
    s[tid] = v;
    __syncthreads();
#pragma unroll
    for (int d = 1; d < 256; d <<= 1) {
        int t = (tid >= d) ? s[tid - d] : 0;
        __syncthreads();
        s[tid] += t;
        __syncthreads();
    }
    if (i < n) off[i] = s[tid] - v;
    if (tid == 255) bsum[blockIdx.x] = s[255];
}

__global__ void scan2(int* __restrict__ bsum, int nb) {
    __shared__ int s[512];
    int tid = threadIdx.x;
    int v = (tid < nb) ? bsum[tid] : 0;
    s[tid] = v;
    __syncthreads();
#pragma unroll
    for (int d = 1; d < 512; d <<= 1) {
        int t = (tid >= d) ? s[tid - d] : 0;
        __syncthreads();
        s[tid] += t;
        __syncthreads();
    }
    if (tid < nb) bsum[tid] = s[tid] - v;
}

__global__ void scan3(int* __restrict__ off, const int* __restrict__ bsum,
                      int* __restrict__ cur, int n, int E) {
    int i = blockIdx.x * 256 + threadIdx.x;
    if (i < n) {
        int o = off[i] + bsum[blockIdx.x];
        off[i] = o;
        cur[i] = o;
    }
    if (i == 0) off[n] = E;
}

__global__ void fill_csr(const int* __restrict__ row, const int* __restrict__ col,
                         int* __restrict__ cur, int* __restrict__ esrc, int E) {
    int e = blockIdx.x * blockDim.x + threadIdx.x;
    if (e < E) {
        int p = atomicAdd(&cur[col[e]], 1);
        esrc[p] = row[e];
    }
}

// ---------------- GEMM: 4 rows x 4 cols / thread, KC=64; fp32 or fp16 output ----------------
template <int K, int N, bool HOUT>
__global__ void gemm_tiled(const float* __restrict__ X, const float* __restrict__ W,
                           const float* __restrict__ dinv, void* __restrict__ Yv, int nrows) {
    constexpr int CG = N / 4;
    constexpr int TR = 4;
    constexpr int RQ = 256 / CG;
    constexpr int ROWS = RQ * TR;
    constexpr int KC = 64;
    constexpr int NCH = K / KC;
    constexpr int XP = KC + 4;
    __shared__ float Xs[ROWS][XP];
    __shared__ float Ws[KC][N];
    int tid = threadIdx.x;
    int row0 = blockIdx.x * ROWS;
    int cg = tid % CG, rq = tid / CG;
    float acc[TR][4] = {};

    for (int ch = 0; ch < NCH; ch++) {
        int k0 = ch * KC;
        for (int j = tid; j < ROWS * (KC / 4); j += 256) {
            int r = j / (KC / 4), kq = j % (KC / 4);
            int gr = row0 + r;
            float4 v = (gr < nrows)
                ? *reinterpret_cast<const float4*>(&X[(size_t)gr * K + k0 + kq * 4])
                : make_float4(0.f, 0.f, 0.f, 0.f);
            *reinterpret_cast<float4*>(&Xs[r][kq * 4]) = v;
        }
        for (int j = tid; j < KC * (N / 4); j += 256) {
            int k = j / (N / 4), nq = j % (N / 4);
            *reinterpret_cast<float4*>(&Ws[k][nq * 4]) =
                *reinterpret_cast<const float4*>(&W[(size_t)(k0 + k) * N + nq * 4]);
        }
        __syncthreads();
#pragma unroll
        for (int k = 0; k < KC; k++) {
            float4 w = *reinterpret_cast<const float4*>(&Ws[k][cg * 4]);
#pragma unroll
            for (int i = 0; i < TR; i++) {
                float xv = Xs[rq * TR + i][k];
                acc[i][0] += xv * w.x;
                acc[i][1] += xv * w.y;
                acc[i][2] += xv * w.z;
                acc[i][3] += xv * w.w;
            }
        }
        __syncthreads();
    }
#pragma unroll
    for (int i = 0; i < TR; i++) {
        int gr = row0 + rq * TR + i;
        if (gr < nrows) {
            float s = dinv ? dinv[gr] : 1.0f;
            if (HOUT) {
                __half2* Y = (__half2*)Yv;
                __half2 p0 = __floats2half2_rn(acc[i][0] * s, acc[i][1] * s);
                __half2 p1 = __floats2half2_rn(acc[i][2] * s, acc[i][3] * s);
                uint2 u;
                u.x = *reinterpret_cast<unsigned*>(&p0);
                u.y = *reinterpret_cast<unsigned*>(&p1);
                *reinterpret_cast<uint2*>(&Y[(size_t)gr * (N / 2) + cg * 2]) = u;
            } else {
                float* Y = (float*)Yv;
                float4 o = make_float4(acc[i][0] * s, acc[i][1] * s, acc[i][2] * s, acc[i][3] * s);
                *reinterpret_cast<float4*>(&Y[(size_t)gr * N + cg * 4]) = o;
            }
        }
    }
}

__device__ __forceinline__ void acc_half4(float4& acc, uint2 u, float w) {
    float2 f0 = __half22float2(*reinterpret_cast<__half2*>(&u.x));
    float2 f1 = __half22float2(*reinterpret_cast<__half2*>(&u.y));
    acc.x += f0.x * w; acc.y += f0.y * w;
    acc.z += f1.x * w; acc.w += f1.y * w;
}

// ---------------- aggregation (fp16 input, fp32 accumulate/output) ----------------
// SCALE_SRC=true: acc = dinv[c]*hls[c] + sum dinv[src]*hls[src]; else pre-scaled sums.
template <bool SCALE_SRC>
__global__ void gather_agg(const int* __restrict__ off, const int* __restrict__ esrc,
                           const __half2* __restrict__ hls, const float* __restrict__ dinv,
                           const float* __restrict__ bias, float* __restrict__ h, int n) {
    __shared__ float sb[64];
    if (threadIdx.x < 64) sb[threadIdx.x] = bias[threadIdx.x];
    __syncthreads();
    int gid = blockIdx.x * 256 + threadIdx.x;
    int c = gid >> 4;
    if (c >= n) return;
    int l = gid & 15;
    const uint2* hp = reinterpret_cast<const uint2*>(hls);  // 4 halves per uint2; 16/node
    float dc = dinv[c];
    float4 acc = make_float4(0.f, 0.f, 0.f, 0.f);
    acc_half4(acc, hp[(size_t)c * 16 + l], SCALE_SRC ? dc : 1.0f);
    int s = off[c], e2 = off[c + 1];
    int j = s;
    for (; j + 1 < e2; j += 2) {
        int r0 = esrc[j], r1 = esrc[j + 1];
        uint2 u0 = hp[(size_t)r0 * 16 + l];
        uint2 u1 = hp[(size_t)r1 * 16 + l];
        acc_half4(acc, u0, SCALE_SRC ? dinv[r0] : 1.0f);
        acc_half4(acc, u1, SCALE_SRC ? dinv[r1] : 1.0f);
    }
    if (j < e2) {
        int r = esrc[j];
        acc_half4(acc, hp[(size_t)r * 16 + l], SCALE_SRC ? dinv[r] : 1.0f);
    }
    int jb = l * 4;
    float4 o;
    o.x = fmaxf(acc.x * dc + sb[jb + 0], 0.f);
    o.y = fmaxf(acc.y * dc + sb[jb + 1], 0.f);
    o.z = fmaxf(acc.z * dc + sb[jb + 2], 0.f);
    o.w = fmaxf(acc.w * dc + sb[jb + 3], 0.f);
    reinterpret_cast<float4*>(h)[(size_t)c * 16 + l] = o;
}

__global__ void repack_wab(const float* __restrict__ l1W, float* __restrict__ wab) {
    int i = blockIdx.x * blockDim.x + threadIdx.x;
    if (i < 64 * 128) {
        int k = i >> 7, nn = i & 127;
        wab[i] = (nn < 64) ? l1W[k * 64 + nn] : l1W[(64 + k) * 64 + (nn - 64)];
    }
}

// per edge: z = relu(A[r]+B[c]+b1); logits = z@L2 + b2; log_softmax(2). ab is fp16.
__global__ void edge_mlp(const int* __restrict__ row, const int* __restrict__ col,
                         const __half2* __restrict__ ab, const float* __restrict__ l1b,
                         const float* __restrict__ l2w, const float* __restrict__ l2b,
                         float* __restrict__ out, int E) {
    __shared__ float s1b[64], s2w[128], s2b[2];
    int tid = threadIdx.x;
    if (tid < 64)        s1b[tid]       = l1b[tid];
    else if (tid < 192)  s2w[tid - 64]  = l2w[tid - 64];
    else if (tid < 194)  s2b[tid - 192] = l2b[tid - 192];
    __syncthreads();
    int gid = blockIdx.x * 256 + tid;
    int e = gid >> 4;
    if (e >= E) return;
    int l = gid & 15;
    int r = row[e], c = col[e];
    const uint2* ap = reinterpret_cast<const uint2*>(ab);  // node row = 32 uint2 (128 halves)
    uint2 ua = ap[(size_t)r * 32 + l];
    uint2 ub = ap[(size_t)c * 32 + 16 + l];
    float2 a0 = __half22float2(*reinterpret_cast<__half2*>(&ua.x));
    float2 a1 = __half22float2(*reinterpret_cast<__half2*>(&ua.y));
    float2 b0 = __half22float2(*reinterpret_cast<__half2*>(&ub.x));
    float2 b1 = __half22float2(*reinterpret_cast<__half2*>(&ub.y));
    int j = l * 4;
    float s0 = 0.f, s1 = 0.f, z;
    z = fmaxf(a0.x + b0.x + s1b[j + 0], 0.f); s0 += z * s2w[(j + 0) * 2]; s1 += z * s2w[(j + 0) * 2 + 1];
    z = fmaxf(a0.y + b0.y + s1b[j + 1], 0.f); s0 += z * s2w[(j + 1) * 2]; s1 += z * s2w[(j + 1) * 2 + 1];
    z = fmaxf(a1.x + b1.x + s1b[j + 2], 0.f); s0 += z * s2w[(j + 2) * 2]; s1 += z * s2w[(j + 2) * 2 + 1];
    z = fmaxf(a1.y + b1.y + s1b[j + 3], 0.f); s0 += z * s2w[(j + 3) * 2]; s1 += z * s2w[(j + 3) * 2 + 1];
#pragma unroll
    for (int off = 8; off > 0; off >>= 1) {
        s0 += __shfl_down_sync(0xFFFFFFFFu, s0, off, 16);
        s1 += __shfl_down_sync(0xFFFFFFFFu, s1, off, 16);
    }
    if (l == 0) {
        s0 += s2b[0]; s1 += s2b[1];
        float m = fmaxf(s0, s1);
        float lse = m + logf(expf(s0 - m) + expf(s1 - m));
        float2 o = make_float2(s0 - lse, s1 - lse);
        *reinterpret_cast<float2*>(&out[2 * (size_t)e]) = o;
    }
}

extern "C" void kernel_launch(void* const* d_in, const int* in_sizes, int n_in,
                              void* d_out, int out_size) {
    const float* x   = (const float*)d_in[0];
    const int*   ei  = (const int*)d_in[1];
    const float* W1  = (const float*)d_in[2];
    const float* b1  = (const float*)d_in[3];
    const float* W2  = (const float*)d_in[4];
    const float* b2  = (const float*)d_in[5];
    const float* l1W = (const float*)d_in[6];
    const float* l1b = (const float*)d_in[7];
    const float* l2W = (const float*)d_in[8];
    const float* l2b = (const float*)d_in[9];
    float* out = (float*)d_out;

    int n = in_sizes[0] / FIN;
    int E = in_sizes[1] / 2;
    const int* row = ei;
    const int* col = ei + E;

    int *cnt, *off, *cur, *esrc, *bsum;
    float *dinv, *h, *wab;
    __half2 *hl2, *ab2;
    cudaGetSymbolAddress((void**)&cnt,  g_cnt);
    cudaGetSymbolAddress((void**)&off,  g_off);
    cudaGetSymbolAddress((void**)&cur,  g_cur);
    cudaGetSymbolAddress((void**)&esrc, g_esrc);
    cudaGetSymbolAddress((void**)&bsum, g_bsum);
    cudaGetSymbolAddress((void**)&dinv, g_dinv);
    cudaGetSymbolAddress((void**)&hl2,  g_hl2);
    cudaGetSymbolAddress((void**)&h,    g_h);
    cudaGetSymbolAddress((void**)&ab2,  g_ab2);
    cudaGetSymbolAddress((void**)&wab,  g_wab);

    const int T = 256;
    int NB = (n + 255) / 256;

    // fork: CSR build + repack on side stream; gemm1 on main
    zero_cnt<<<NB, T>>>(cnt, n);
    cudaEventRecord(g_evFork, 0);
    cudaStreamWaitEvent(g_s2, g_evFork, 0);
    count_in<<<(E + T - 1) / T, T, 0, g_s2>>>(col, cnt, E);
    scan1<<<NB, T, 0, g_s2>>>(cnt, off, bsum, dinv, n);
    scan2<<<1, 512, 0, g_s2>>>(bsum, NB);
    scan3<<<NB, T, 0, g_s2>>>(off, bsum, cur, n, E);
    fill_csr<<<(E + T - 1) / T, T, 0, g_s2>>>(row, col, cur, esrc, E);
    repack_wab<<<(64 * 128 + T - 1) / T, T, 0, g_s2>>>(l1W, wab);
    cudaEventRecord(g_evJoin, g_s2);

    // gemm1 overlaps CSR chain (unscaled, fp16 out)
    gemm_tiled<128, 64, true><<<(n + 63) / 64, 256>>>(x, W1, (const float*)nullptr, hl2, n);
    cudaStreamWaitEvent(0, g_evJoin, 0);

    gather_agg<true><<<(n * 16 + T - 1) / T, T>>>(off, esrc, hl2, dinv, b1, h, n);

    gemm_tiled<64, 64, true><<<(n + 63) / 64, 256>>>(h, W2, dinv, hl2, n);
    gather_agg<false><<<(n * 16 + T - 1) / T, T>>>(off, esrc, hl2, dinv, b2, h, n);

    gemm_tiled<64, 128, true><<<(n + 31) / 32, 256>>>(h, wab, (const float*)nullptr, ab2, n);
    edge_mlp<<<(E * 16 + T - 1) / T, T>>>(row, col, ab2, l1b, l2W, l2b, out, E);
}

// round 8
// speedup vs baseline: 1.2528x; 1.1546x over previous
#include <cuda_runtime.h>
#include <cuda_fp16.h>

#define NMAX 100000
#define EMAX 1600000
#define HIDD 64
#define FIN  128

__device__ int     g_cnt[NMAX];
__device__ int     g_off[NMAX + 1];
__device__ int     g_cur[NMAX];
__device__ int     g_esrc[EMAX];
__device__ int     g_bsum[512];
__device__ float   g_dinv[NMAX];
__device__ __half2 g_hl2[NMAX * HIDD / 2];   // fp16 linear features (gather input)
__device__ float   g_h [NMAX * HIDD];        // aggregated features (fp32)
__device__ __half2 g_ab2[NMAX * HIDD];       // fp16 [A|B] table (edge_mlp input)
__device__ __half  g_w1h[FIN * HIDD];
__device__ __half  g_w2h[HIDD * HIDD];
__device__ __half  g_wabh[HIDD * 2 * HIDD];  // repacked lin1_W, fp16 [64][128]

static cudaStream_t g_s2;
static cudaEvent_t g_evFork, g_evJoin;
namespace { struct StreamInit {
    StreamInit() {
        cudaStreamCreateWithFlags(&g_s2, cudaStreamNonBlocking);
        cudaEventCreateWithFlags(&g_evFork, cudaEventDisableTiming);
        cudaEventCreateWithFlags(&g_evJoin, cudaEventDisableTiming);
    }
} g_streamInit; }

// ---------------- CSC build ----------------
__global__ void zero_cnt(int* __restrict__ cnt, int n) {
    int i = blockIdx.x * blockDim.x + threadIdx.x;
    if (i < n) cnt[i] = 0;
}
__global__ void count_in(const int* __restrict__ col, int* __restrict__ cnt, int E) {
    int e = blockIdx.x * blockDim.x + threadIdx.x;
    if (e < E) atomicAdd(&cnt[col[e]], 1);
}
__global__ void scan1(const int* __restrict__ cnt, int* __restrict__ off,
                      int* __restrict__ bsum, float* __restrict__ dinv, int n) {
    __shared__ int s[256];
    int tid = threadIdx.x;
    int i = blockIdx.x * 256 + tid;
    int v = (i < n) ? cnt[i] : 0;
    if (i < n) dinv[i] = rsqrtf((float)v + 1.0f);
    s[tid] = v;
    __syncthreads();
#pragma unroll
    for (int d = 1; d < 256; d <<= 1) {
        int t = (tid >= d) ? s[tid - d] : 0;
        __syncthreads();
        s[tid] += t;
        __syncthreads();
    }
    if (i < n) off[i] = s[tid] - v;
    if (tid == 255) bsum[blockIdx.x] = s[255];
}
__global__ void scan2(int* __restrict__ bsum, int nb) {
    __shared__ int s[512];
    int tid = threadIdx.x;
    int v = (tid < nb) ? bsum[tid] : 0;
    s[tid] = v;
    __syncthreads();
#pragma unroll
    for (int d = 1; d < 512; d <<= 1) {
        int t = (tid >= d) ? s[tid - d] : 0;
        __syncthreads();
        s[tid] += t;
        __syncthreads();
    }
    if (tid < nb) bsum[tid] = s[tid] - v;
}
__global__ void scan3(int* __restrict__ off, const int* __restrict__ bsum,
                      int* __restrict__ cur, int n, int E) {
    int i = blockIdx.x * 256 + threadIdx.x;
    if (i < n) {
        int o = off[i] + bsum[blockIdx.x];
        off[i] = o;
        cur[i] = o;
    }
    if (i == 0) off[n] = E;
}
__global__ void fill_csr(const int* __restrict__ row, const int* __restrict__ col,
                         int* __restrict__ cur, int* __restrict__ esrc, int E) {
    int e = blockIdx.x * blockDim.x + threadIdx.x;
    if (e < E) {
        int p = atomicAdd(&cur[col[e]], 1);
        esrc[p] = row[e];
    }
}

// ---------------- weight conversion ----------------
__global__ void conv_w(const float* __restrict__ src, __half* __restrict__ dst, int count) {
    int i = blockIdx.x * blockDim.x + threadIdx.x;
    if (i < count) dst[i] = __float2half_rn(src[i]);
}
__global__ void repack_wab_h(const float* __restrict__ l1W, __half* __restrict__ wabh) {
    int i = blockIdx.x * blockDim.x + threadIdx.x;
    if (i < 64 * 128) {
        int k = i >> 7, nn = i & 127;
        float v = (nn < 64) ? l1W[k * 64 + nn] : l1W[(64 + k) * 64 + (nn - 64)];
        wabh[i] = __float2half_rn(v);
    }
}

// ---------------- HMMA GEMM ----------------
// Y(half2)[nrows,N/2] = to_half( (X[nrows,K] @ Wh[K,N]) * (SCALE ? dinv[r] : 1) )
// 128 threads (4 warps), 64 rows/block. mma.m16n8k16 f32.f16.f16.f32.
template <int K, int N, bool SCALE>
__global__ void gemm_mma(const float* __restrict__ X, const __half* __restrict__ Wh,
                         const float* __restrict__ dinv, __half2* __restrict__ Y, int nrows) {
    constexpr int XP = K + 8;   // half units; row stride (K+8)*2 bytes -> conflict-free ldmatrix
    constexpr int WP = N + 8;
    __shared__ __half Xs[64 * XP];
    __shared__ __half Ws[K * WP];
    int tid = threadIdx.x;
    int warp = tid >> 5, lane = tid & 31;
    int row0 = blockIdx.x * 64;

    // stage X fp32 -> fp16
    for (int j = tid; j < 64 * (K / 4); j += 128) {
        int r = j / (K / 4), kq = j % (K / 4);
        int gr = row0 + r;
        float4 v = (gr < nrows)
            ? *reinterpret_cast<const float4*>(&X[(size_t)gr * K + kq * 4])
            : make_float4(0.f, 0.f, 0.f, 0.f);
        __half2 h0 = __floats2half2_rn(v.x, v.y);
        __half2 h1 = __floats2half2_rn(v.z, v.w);
        uint2 u;
        u.x = *reinterpret_cast<unsigned*>(&h0);
        u.y = *reinterpret_cast<unsigned*>(&h1);
        *reinterpret_cast<uint2*>(&Xs[r * XP + kq * 4]) = u;
    }
    // stage W (fp16, packed [K][N])
    for (int j = tid; j < K * (N / 8); j += 128) {
        int k = j / (N / 8), nq = j % (N / 8);
        *reinterpret_cast<uint4*>(&Ws[k * WP + nq * 8]) =
            *reinterpret_cast<const uint4*>(&Wh[(size_t)k * N + nq * 8]);
    }
    __syncthreads();

    float acc[N / 8][4];
#pragma unroll
    for (int nt = 0; nt < N / 8; nt++)
#pragma unroll
        for (int q = 0; q < 4; q++) acc[nt][q] = 0.f;

    // A ldmatrix lane mapping: row = warp*16 + lane%16, col = kt*16 + (lane/16)*8
    int arow = warp * 16 + (lane & 15);
    int acol = (lane >> 4) * 8;
    int brow_l = lane & 15;  // B: row kt*16 + lane%16 (first 16 lanes consumed by x2)

#pragma unroll
    for (int kt = 0; kt < K / 16; kt++) {
        unsigned a0, a1, a2, a3;
        unsigned aaddr = (unsigned)__cvta_generic_to_shared(&Xs[arow * XP + kt * 16 + acol]);
        asm volatile("ldmatrix.sync.aligned.m8n8.x4.shared.b16 {%0,%1,%2,%3}, [%4];"
                     : "=r"(a0), "=r"(a1), "=r"(a2), "=r"(a3) : "r"(aaddr));
#pragma unroll
        for (int nt = 0; nt < N / 8; nt++) {
            unsigned b0, b1;
            unsigned baddr = (unsigned)__cvta_generic_to_shared(
                &Ws[(kt * 16 + brow_l) * WP + nt * 8]);
            asm volatile("ldmatrix.sync.aligned.m8n8.x2.trans.shared.b16 {%0,%1}, [%2];"
                         : "=r"(b0), "=r"(b1) : "r"(baddr));
            asm volatile(
                "mma.sync.aligned.m16n8k16.row.col.f32.f16.f16.f32 "
                "{%0,%1,%2,%3}, {%4,%5,%6,%7}, {%8,%9}, {%0,%1,%2,%3};"
                : "+f"(acc[nt][0]), "+f"(acc[nt][1]), "+f"(acc[nt][2]), "+f"(acc[nt][3])
                : "r"(a0), "r"(a1), "r"(a2), "r"(a3), "r"(b0), "r"(b1));
        }
    }

    // epilogue: c0,c1 -> row lane/4, cols (lane%4)*2 +{0,1}; c2,c3 -> row lane/4+8
    int rr = warp * 16 + (lane >> 2);
    int cq = lane & 3;
#pragma unroll
    for (int hh = 0; hh < 2; hh++) {
        int gr = row0 + rr + hh * 8;
        if (gr < nrows) {
            float s = SCALE ? dinv[gr] : 1.0f;
#pragma unroll
            for (int nt = 0; nt < N / 8; nt++) {
                __half2 p = __floats2half2_rn(acc[nt][hh * 2 + 0] * s,
                                              acc[nt][hh * 2 + 1] * s);
                Y[(size_t)gr * (N / 2) + nt * 4 + cq] = p;
            }
        }
    }
}

__device__ __forceinline__ void acc_half4(float4& acc, uint2 u, float w) {
    float2 f0 = __half22float2(*reinterpret_cast<__half2*>(&u.x));
    float2 f1 = __half22float2(*reinterpret_cast<__half2*>(&u.y));
    acc.x += f0.x * w; acc.y += f0.y * w;
    acc.z += f1.x * w; acc.w += f1.y * w;
}

// ---------------- aggregation (fp16 input, fp32 accumulate/output) ----------------
template <bool SCALE_SRC>
__global__ void gather_agg(const int* __restrict__ off, const int* __restrict__ esrc,
                           const __half2* __restrict__ hls, const float* __restrict__ dinv,
                           const float* __restrict__ bias, float* __restrict__ h, int n) {
    __shared__ float sb[64];
    if (threadIdx.x < 64) sb[threadIdx.x] = bias[threadIdx.x];
    __syncthreads();
    int gid = blockIdx.x * 256 + threadIdx.x;
    int c = gid >> 4;
    if (c >= n) return;
    int l = gid & 15;
    const uint2* hp = reinterpret_cast<const uint2*>(hls);
    float dc = dinv[c];
    float4 acc = make_float4(0.f, 0.f, 0.f, 0.f);
    acc_half4(acc, hp[(size_t)c * 16 + l], SCALE_SRC ? dc : 1.0f);
    int s = off[c], e2 = off[c + 1];
    int j = s;
    for (; j + 1 < e2; j += 2) {
        int r0 = esrc[j], r1 = esrc[j + 1];
        uint2 u0 = hp[(size_t)r0 * 16 + l];
        uint2 u1 = hp[(size_t)r1 * 16 + l];
        acc_half4(acc, u0, SCALE_SRC ? dinv[r0] : 1.0f);
        acc_half4(acc, u1, SCALE_SRC ? dinv[r1] : 1.0f);
    }
    if (j < e2) {
        int r = esrc[j];
        acc_half4(acc, hp[(size_t)r * 16 + l], SCALE_SRC ? dinv[r] : 1.0f);
    }
    int jb = l * 4;
    float4 o;
    o.x = fmaxf(acc.x * dc + sb[jb + 0], 0.f);
    o.y = fmaxf(acc.y * dc + sb[jb + 1], 0.f);
    o.z = fmaxf(acc.z * dc + sb[jb + 2], 0.f);
    o.w = fmaxf(acc.w * dc + sb[jb + 3], 0.f);
    reinterpret_cast<float4*>(h)[(size_t)c * 16 + l] = o;
}

// per edge: z = relu(A[r]+B[c]+b1); logits = z@L2 + b2; log_softmax(2). ab is fp16.
__global__ void edge_mlp(const int* __restrict__ row, const int* __restrict__ col,
                         const __half2* __restrict__ ab, const float* __restrict__ l1b,
                         const float* __restrict__ l2w, const float* __restrict__ l2b,
                         float* __restrict__ out, int E) {
    __shared__ float s1b[64], s2w[128], s2b[2];
    int tid = threadIdx.x;
    if (tid < 64)        s1b[tid]       = l1b[tid];
    else if (tid < 192)  s2w[tid - 64]  = l2w[tid - 64];
    else if (tid < 194)  s2b[tid - 192] = l2b[tid - 192];
    __syncthreads();
    int gid = blockIdx.x * 256 + tid;
    int e = gid >> 4;
    if (e >= E) return;
    int l = gid & 15;
    int r = row[e], c = col[e];
    const uint2* ap = reinterpret_cast<const uint2*>(ab);
    uint2 ua = ap[(size_t)r * 32 + l];
    uint2 ub = ap[(size_t)c * 32 + 16 + l];
    float2 a0 = __half22float2(*reinterpret_cast<__half2*>(&ua.x));
    float2 a1 = __half22float2(*reinterpret_cast<__half2*>(&ua.y));
    float2 b0 = __half22float2(*reinterpret_cast<__half2*>(&ub.x));
    float2 b1 = __half22float2(*reinterpret_cast<__half2*>(&ub.y));
    int j = l * 4;
    float s0 = 0.f, s1 = 0.f, z;
    z = fmaxf(a0.x + b0.x + s1b[j + 0], 0.f); s0 += z * s2w[(j + 0) * 2]; s1 += z * s2w[(j + 0) * 2 + 1];
    z = fmaxf(a0.y + b0.y + s1b[j + 1], 0.f); s0 += z * s2w[(j + 1) * 2]; s1 += z * s2w[(j + 1) * 2 + 1];
    z = fmaxf(a1.x + b1.x + s1b[j + 2], 0.f); s0 += z * s2w[(j + 2) * 2]; s1 += z * s2w[(j + 2) * 2 + 1];
    z = fmaxf(a1.y + b1.y + s1b[j + 3], 0.f); s0 += z * s2w[(j + 3) * 2]; s1 += z * s2w[(j + 3) * 2 + 1];
#pragma unroll
    for (int off = 8; off > 0; off >>= 1) {
        s0 += __shfl_down_sync(0xFFFFFFFFu, s0, off, 16);
        s1 += __shfl_down_sync(0xFFFFFFFFu, s1, off, 16);
    }
    if (l == 0) {
        s0 += s2b[0]; s1 += s2b[1];
        float m = fmaxf(s0, s1);
        float lse = m + logf(expf(s0 - m) + expf(s1 - m));
        float2 o = make_float2(s0 - lse, s1 - lse);
        *reinterpret_cast<float2*>(&out[2 * (size_t)e]) = o;
    }
}

extern "C" void kernel_launch(void* const* d_in, const int* in_sizes, int n_in,
                              void* d_out, int out_size) {
    const float* x   = (const float*)d_in[0];
    const int*   ei  = (const int*)d_in[1];
    const float* W1  = (const float*)d_in[2];
    const float* b1  = (const float*)d_in[3];
    const float* W2  = (const float*)d_in[4];
    const float* b2  = (const float*)d_in[5];
    const float* l1W = (const float*)d_in[6];
    const float* l1b = (const float*)d_in[7];
    const float* l2W = (const float*)d_in[8];
    const float* l2b = (const float*)d_in[9];
    float* out = (float*)d_out;

    int n = in_sizes[0] / FIN;
    int E = in_sizes[1] / 2;
    const int* row = ei;
    const int* col = ei + E;

    int *cnt, *off, *cur, *esrc, *bsum;
    float *dinv, *h;
    __half2 *hl2, *ab2;
    __half *w1h, *w2h, *wabh;
    cudaGetSymbolAddress((void**)&cnt,  g_cnt);
    cudaGetSymbolAddress((void**)&off,  g_off);
    cudaGetSymbolAddress((void**)&cur,  g_cur);
    cudaGetSymbolAddress((void**)&esrc, g_esrc);
    cudaGetSymbolAddress((void**)&bsum, g_bsum);
    cudaGetSymbolAddress((void**)&dinv, g_dinv);
    cudaGetSymbolAddress((void**)&hl2,  g_hl2);
    cudaGetSymbolAddress((void**)&h,    g_h);
    cudaGetSymbolAddress((void**)&ab2,  g_ab2);
    cudaGetSymbolAddress((void**)&w1h,  g_w1h);
    cudaGetSymbolAddress((void**)&w2h,  g_w2h);
    cudaGetSymbolAddress((void**)&wabh, g_wabh);

    const int T = 256;
    int NB = (n + 255) / 256;

    // fork: CSR build + weight conversions on side stream; gemm1 path on main
    zero_cnt<<<NB, T>>>(cnt, n);
    cudaEventRecord(g_evFork, 0);
    cudaStreamWaitEvent(g_s2, g_evFork, 0);
    count_in<<<(E + T - 1) / T, T, 0, g_s2>>>(col, cnt, E);
    scan1<<<NB, T, 0, g_s2>>>(cnt, off, bsum, dinv, n);
    scan2<<<1, 512, 0, g_s2>>>(bsum, NB);
    scan3<<<NB, T, 0, g_s2>>>(off, bsum, cur, n, E);
    fill_csr<<<(E + T - 1) / T, T, 0, g_s2>>>(row, col, cur, esrc, E);
    conv_w<<<(HIDD * HIDD + T - 1) / T, T, 0, g_s2>>>(W2, w2h, HIDD * HIDD);
    repack_wab_h<<<(64 * 128 + T - 1) / T, T, 0, g_s2>>>(l1W, wabh);
    cudaEventRecord(g_evJoin, g_s2);

    // main: convert W1, then gemm1 (unscaled fp16 out) overlapping the CSR chain
    conv_w<<<(FIN * HIDD + T - 1) / T, T>>>(W1, w1h, FIN * HIDD);
    gemm_mma<128, 64, false><<<(n + 63) / 64, 128>>>(x, w1h, (const float*)nullptr, hl2, n);
    cudaStreamWaitEvent(0, g_evJoin, 0);

    gather_agg<true><<<(n * 16 + T - 1) / T, T>>>(off, esrc, hl2, dinv, b1, h, n);

    gemm_mma<64, 64, true><<<(n + 63) / 64, 128>>>(h, w2h, dinv, hl2, n);
    gather_agg<false><<<(n * 16 + T - 1) / T, T>>>(off, esrc, hl2, dinv, b2, h, n);

    gemm_mma<64, 128, false><<<(n + 63) / 64, 128>>>(h, wabh, (const float*)nullptr, ab2, n);
    edge_mlp<<<(E * 16 + T - 1) / T, T>>>(row, col, ab2, l1b, l2W, l2b, out, E);
}

// round 9
// speedup vs baseline: 1.3318x; 1.0630x over previous
#include <cuda_runtime.h>
#include <cuda_fp16.h>

#define NMAX 100000
#define EMAX 1600000
#define HIDD 64
#define FIN  128

__device__ int     g_cnt[NMAX];
__device__ int     g_off[NMAX + 1];
__device__ int     g_cur[NMAX];
__device__ int     g_esrc[EMAX];
__device__ int     g_bsum[512];
__device__ float   g_dinv[NMAX];
__device__ __half2 g_hl2[NMAX * HIDD / 2];   // fp16 linear features (gather input)
__device__ __half2 g_h2 [NMAX * HIDD / 2];   // fp16 aggregated features
__device__ __half2 g_ab2[NMAX * HIDD];       // fp16 [A|B] table (edge_mlp input)
__device__ __half  g_w1h[FIN * HIDD];
__device__ __half  g_w2h[HIDD * HIDD];
__device__ __half  g_wabh[HIDD * 2 * HIDD];

static cudaStream_t g_s2;
static cudaEvent_t g_evFork, g_evJoin;
namespace { struct StreamInit {
    StreamInit() {
        cudaStreamCreateWithFlags(&g_s2, cudaStreamNonBlocking);
        cudaEventCreateWithFlags(&g_evFork, cudaEventDisableTiming);
        cudaEventCreateWithFlags(&g_evJoin, cudaEventDisableTiming);
    }
} g_streamInit; }

// ---------------- CSC build ----------------
__global__ void zero_cnt(int* __restrict__ cnt, int n) {
    int i = blockIdx.x * blockDim.x + threadIdx.x;
    if (i < n) cnt[i] = 0;
}
__global__ void count_in(const int* __restrict__ col, int* __restrict__ cnt, int E) {
    int e = blockIdx.x * blockDim.x + threadIdx.x;
    if (e < E) atomicAdd(&cnt[col[e]], 1);
}
__global__ void scan1(const int* __restrict__ cnt, int* __restrict__ off,
                      int* __restrict__ bsum, float* __restrict__ dinv, int n) {
    __shared__ int s[256];
    int tid = threadIdx.x;
    int i = blockIdx.x * 256 + tid;
    int v = (i < n) ? cnt[i] : 0;
    if (i < n) dinv[i] = rsqrtf((float)v + 1.0f);
    s[tid] = v;
    __syncthreads();
#pragma unroll
    for (int d = 1; d < 256; d <<= 1) {
        int t = (tid >= d) ? s[tid - d] : 0;
        __syncthreads();
        s[tid] += t;
        __syncthreads();
    }
    if (i < n) off[i] = s[tid] - v;
    if (tid == 255) bsum[blockIdx.x] = s[255];
}
__global__ void scan2(int* __restrict__ bsum, int nb) {
    __shared__ int s[512];
    int tid = threadIdx.x;
    int v = (tid < nb) ? bsum[tid] : 0;
    s[tid] = v;
    __syncthreads();
#pragma unroll
    for (int d = 1; d < 512; d <<= 1) {
        int t = (tid >= d) ? s[tid - d] : 0;
        __syncthreads();
        s[tid] += t;
        __syncthreads();
    }
    if (tid < nb) bsum[tid] = s[tid] - v;
}
__global__ void scan3(int* __restrict__ off, const int* __restrict__ bsum,
                      int* __restrict__ cur, int n, int E) {
    int i = blockIdx.x * 256 + threadIdx.x;
    if (i < n) {
        int o = off[i] + bsum[blockIdx.x];
        off[i] = o;
        cur[i] = o;
    }
    if (i == 0) off[n] = E;
}
__global__ void fill_csr(const int* __restrict__ row, const int* __restrict__ col,
                         int* __restrict__ cur, int* __restrict__ esrc, int E) {
    int e = blockIdx.x * blockDim.x + threadIdx.x;
    if (e < E) {
        int p = atomicAdd(&cur[col[e]], 1);
        esrc[p] = row[e];
    }
}

// ---------------- weight conversion ----------------
__global__ void conv_w(const float* __restrict__ src, __half* __restrict__ dst, int count) {
    int i = blockIdx.x * blockDim.x + threadIdx.x;
    if (i < count) dst[i] = __float2half_rn(src[i]);
}
__global__ void repack_wab_h(const float* __restrict__ l1W, __half* __restrict__ wabh) {
    int i = blockIdx.x * blockDim.x + threadIdx.x;
    if (i < 64 * 128) {
        int k = i >> 7, nn = i & 127;
        float v = (nn < 64) ? l1W[k * 64 + nn] : l1W[(64 + k) * 64 + (nn - 64)];
        wabh[i] = __float2half_rn(v);
    }
}

// ---------------- HMMA GEMM ----------------
// Y(half2) = to_half( (X @ Wh) * (SCALE ? dinv[r] : 1) ); X fp32 or fp16 (HALF_IN)
template <int K, int N, bool SCALE, bool HALF_IN>
__global__ void gemm_mma(const void* __restrict__ Xv, const __half* __restrict__ Wh,
                         const float* __restrict__ dinv, __half2* __restrict__ Y, int nrows) {
    constexpr int XP = K + 8;
    constexpr int WP = N + 8;
    __shared__ __half Xs[64 * XP];
    __shared__ __half Ws[K * WP];
    int tid = threadIdx.x;
    int warp = tid >> 5, lane = tid & 31;
    int row0 = blockIdx.x * 64;

    if (HALF_IN) {
        const __half* X = (const __half*)Xv;
        for (int j = tid; j < 64 * (K / 8); j += 128) {
            int r = j / (K / 8), kq = j % (K / 8);
            int gr = row0 + r;
            uint4 u = make_uint4(0, 0, 0, 0);
            if (gr < nrows) u = *reinterpret_cast<const uint4*>(&X[(size_t)gr * K + kq * 8]);
            *reinterpret_cast<uint4*>(&Xs[r * XP + kq * 8]) = u;
        }
    } else {
        const float* X = (const float*)Xv;
        for (int j = tid; j < 64 * (K / 4); j += 128) {
            int r = j / (K / 4), kq = j % (K / 4);
            int gr = row0 + r;
            float4 v = (gr < nrows)
                ? *reinterpret_cast<const float4*>(&X[(size_t)gr * K + kq * 4])
                : make_float4(0.f, 0.f, 0.f, 0.f);
            __half2 h0 = __floats2half2_rn(v.x, v.y);
            __half2 h1 = __floats2half2_rn(v.z, v.w);
            uint2 u;
            u.x = *reinterpret_cast<unsigned*>(&h0);
            u.y = *reinterpret_cast<unsigned*>(&h1);
            *reinterpret_cast<uint2*>(&Xs[r * XP + kq * 4]) = u;
        }
    }
    for (int j = tid; j < K * (N / 8); j += 128) {
        int k = j / (N / 8), nq = j % (N / 8);
        *reinterpret_cast<uint4*>(&Ws[k * WP + nq * 8]) =
            *reinterpret_cast<const uint4*>(&Wh[(size_t)k * N + nq * 8]);
    }
    __syncthreads();

    float acc[N / 8][4];
#pragma unroll
    for (int nt = 0; nt < N / 8; nt++)
#pragma unroll
        for (int q = 0; q < 4; q++) acc[nt][q] = 0.f;

    int arow = warp * 16 + (lane & 15);
    int acol = (lane >> 4) * 8;
    int brow_l = lane & 15;

#pragma unroll
    for (int kt = 0; kt < K / 16; kt++) {
        unsigned a0, a1, a2, a3;
        unsigned aaddr = (unsigned)__cvta_generic_to_shared(&Xs[arow * XP + kt * 16 + acol]);
        asm volatile("ldmatrix.sync.aligned.m8n8.x4.shared.b16 {%0,%1,%2,%3}, [%4];"
                     : "=r"(a0), "=r"(a1), "=r"(a2), "=r"(a3) : "r"(aaddr));
#pragma unroll
        for (int nt = 0; nt < N / 8; nt++) {
            unsigned b0, b1;
            unsigned baddr = (unsigned)__cvta_generic_to_shared(
                &Ws[(kt * 16 + brow_l) * WP + nt * 8]);
            asm volatile("ldmatrix.sync.aligned.m8n8.x2.trans.shared.b16 {%0,%1}, [%2];"
                         : "=r"(b0), "=r"(b1) : "r"(baddr));
            asm volatile(
                "mma.sync.aligned.m16n8k16.row.col.f32.f16.f16.f32 "
                "{%0,%1,%2,%3}, {%4,%5,%6,%7}, {%8,%9}, {%0,%1,%2,%3};"
                : "+f"(acc[nt][0]), "+f"(acc[nt][1]), "+f"(acc[nt][2]), "+f"(acc[nt][3])
                : "r"(a0), "r"(a1), "r"(a2), "r"(a3), "r"(b0), "r"(b1));
        }
    }

    int rr = warp * 16 + (lane >> 2);
    int cq = lane & 3;
#pragma unroll
    for (int hh = 0; hh < 2; hh++) {
        int gr = row0 + rr + hh * 8;
        if (gr < nrows) {
            float s = SCALE ? dinv[gr] : 1.0f;
#pragma unroll
            for (int nt = 0; nt < N / 8; nt++) {
                __half2 p = __floats2half2_rn(acc[nt][hh * 2 + 0] * s,
                                              acc[nt][hh * 2 + 1] * s);
                Y[(size_t)gr * (N / 2) + nt * 4 + cq] = p;
            }
        }
    }
}

__device__ __forceinline__ void acc_half8(float4& a, float4& b, uint4 u, float w) {
    float2 f0 = __half22float2(*reinterpret_cast<__half2*>(&u.x));
    float2 f1 = __half22float2(*reinterpret_cast<__half2*>(&u.y));
    float2 f2 = __half22float2(*reinterpret_cast<__half2*>(&u.z));
    float2 f3 = __half22float2(*reinterpret_cast<__half2*>(&u.w));
    a.x += f0.x * w; a.y += f0.y * w; a.z += f1.x * w; a.w += f1.y * w;
    b.x += f2.x * w; b.y += f2.y * w; b.z += f3.x * w; b.w += f3.y * w;
}

// ---------------- aggregation: 8 lanes/node, uint4 (8 halves) per lane ----------------
template <bool SCALE_SRC>
__global__ void gather_agg(const int* __restrict__ off, const int* __restrict__ esrc,
                           const __half2* __restrict__ hls, const float* __restrict__ dinv,
                           const float* __restrict__ bias, __half2* __restrict__ h, int n) {
    __shared__ float sb[64];
    if (threadIdx.x < 64) sb[threadIdx.x] = bias[threadIdx.x];
    __syncthreads();
    int gid = blockIdx.x * 256 + threadIdx.x;
    int c = gid >> 3;
    if (c >= n) return;
    int l = gid & 7;
    const uint4* hp = reinterpret_cast<const uint4*>(hls);  // node row = 8 uint4
    float dc = dinv[c];
    float4 a = make_float4(0.f, 0.f, 0.f, 0.f);
    float4 b = make_float4(0.f, 0.f, 0.f, 0.f);
    acc_half8(a, b, hp[(size_t)c * 8 + l], SCALE_SRC ? dc : 1.0f);
    int s = off[c], e2 = off[c + 1];
    int j = s;
    for (; j + 1 < e2; j += 2) {
        int r0 = esrc[j], r1 = esrc[j + 1];
        uint4 u0 = hp[(size_t)r0 * 8 + l];
        uint4 u1 = hp[(size_t)r1 * 8 + l];
        acc_half8(a, b, u0, SCALE_SRC ? dinv[r0] : 1.0f);
        acc_half8(a, b, u1, SCALE_SRC ? dinv[r1] : 1.0f);
    }
    if (j < e2) {
        int r = esrc[j];
        acc_half8(a, b, hp[(size_t)r * 8 + l], SCALE_SRC ? dinv[r] : 1.0f);
    }
    int jb = l * 8;
    __half2 p0 = __floats2half2_rn(fmaxf(a.x * dc + sb[jb + 0], 0.f), fmaxf(a.y * dc + sb[jb + 1], 0.f));
    __half2 p1 = __floats2half2_rn(fmaxf(a.z * dc + sb[jb + 2], 0.f), fmaxf(a.w * dc + sb[jb + 3], 0.f));
    __half2 p2 = __floats2half2_rn(fmaxf(b.x * dc + sb[jb + 4], 0.f), fmaxf(b.y * dc + sb[jb + 5], 0.f));
    __half2 p3 = __floats2half2_rn(fmaxf(b.z * dc + sb[jb + 6], 0.f), fmaxf(b.w * dc + sb[jb + 7], 0.f));
    uint4 o;
    o.x = *reinterpret_cast<unsigned*>(&p0);
    o.y = *reinterpret_cast<unsigned*>(&p1);
    o.z = *reinterpret_cast<unsigned*>(&p2);
    o.w = *reinterpret_cast<unsigned*>(&p3);
    reinterpret_cast<uint4*>(h)[(size_t)c * 8 + l] = o;
}

// ---------------- edge MLP: 8 lanes/edge, 8 dims per lane ----------------
__global__ void edge_mlp(const int* __restrict__ row, const int* __restrict__ col,
                         const __half2* __restrict__ ab, const float* __restrict__ l1b,
                         const float* __restrict__ l2w, const float* __restrict__ l2b,
                         float* __restrict__ out, int E) {
    __shared__ float s1b[64], s2w[128], s2b[2];
    int tid = threadIdx.x;
    if (tid < 64)        s1b[tid]       = l1b[tid];
    else if (tid < 192)  s2w[tid - 64]  = l2w[tid - 64];
    else if (tid < 194)  s2b[tid - 192] = l2b[tid - 192];
    __syncthreads();
    int gid = blockIdx.x * 256 + tid;
    int e = gid >> 3;
    if (e >= E) return;
    int l = gid & 7;
    int r = row[e], c = col[e];
    const uint4* ap = reinterpret_cast<const uint4*>(ab);  // node row = 16 uint4 (128 halves)
    uint4 ua = ap[(size_t)r * 16 + l];
    uint4 ub = ap[(size_t)c * 16 + 8 + l];
    float2 a0 = __half22float2(*reinterpret_cast<__half2*>(&ua.x));
    float2 a1 = __half22float2(*reinterpret_cast<__half2*>(&ua.y));
    float2 a2 = __half22float2(*reinterpret_cast<__half2*>(&ua.z));
    float2 a3 = __half22float2(*reinterpret_cast<__half2*>(&ua.w));
    float2 b0 = __half22float2(*reinterpret_cast<__half2*>(&ub.x));
    float2 b1 = __half22float2(*reinterpret_cast<__half2*>(&ub.y));
    float2 b2 = __half22float2(*reinterpret_cast<__half2*>(&ub.z));
    float2 b3 = __half22float2(*reinterpret_cast<__half2*>(&ub.w));
    int j = l * 8;
    float s0 = 0.f, s1 = 0.f, z;
    z = fmaxf(a0.x + b0.x + s1b[j + 0], 0.f); s0 += z * s2w[(j + 0) * 2]; s1 += z * s2w[(j + 0) * 2 + 1];
    z = fmaxf(a0.y + b0.y + s1b[j + 1], 0.f); s0 += z * s2w[(j + 1) * 2]; s1 += z * s2w[(j + 1) * 2 + 1];
    z = fmaxf(a1.x + b1.x + s1b[j + 2], 0.f); s0 += z * s2w[(j + 2) * 2]; s1 += z * s2w[(j + 2) * 2 + 1];
    z = fmaxf(a1.y + b1.y + s1b[j + 3], 0.f); s0 += z * s2w[(j + 3) * 2]; s1 += z * s2w[(j + 3) * 2 + 1];
    z = fmaxf(a2.x + b2.x + s1b[j + 4], 0.f); s0 += z * s2w[(j + 4) * 2]; s1 += z * s2w[(j + 4) * 2 + 1];
    z = fmaxf(a2.y + b2.y + s1b[j + 5], 0.f); s0 += z * s2w[(j + 5) * 2]; s1 += z * s2w[(j + 5) * 2 + 1];
    z = fmaxf(a3.x + b3.x + s1b[j + 6], 0.f); s0 += z * s2w[(j + 6) * 2]; s1 += z * s2w[(j + 6) * 2 + 1];
    z = fmaxf(a3.y + b3.y + s1b[j + 7], 0.f); s0 += z * s2w[(j + 7) * 2]; s1 += z * s2w[(j + 7) * 2 + 1];
#pragma unroll
    for (int off = 4; off > 0; off >>= 1) {
        s0 += __shfl_down_sync(0xFFFFFFFFu, s0, off, 8);
        s1 += __shfl_down_sync(0xFFFFFFFFu, s1, off, 8);
    }
    if (l == 0) {
        s0 += s2b[0]; s1 += s2b[1];
        float m = fmaxf(s0, s1);
        float lse = m + logf(expf(s0 - m) + expf(s1 - m));
        float2 o = make_float2(s0 - lse, s1 - lse);
        *reinterpret_cast<float2*>(&out[2 * (size_t)e]) = o;
    }
}

extern "C" void kernel_launch(void* const* d_in, const int* in_sizes, int n_in,
                              void* d_out, int out_size) {
    const float* x   = (const float*)d_in[0];
    const int*   ei  = (const int*)d_in[1];
    const float* W1  = (const float*)d_in[2];
    const float* b1  = (const float*)d_in[3];
    const float* W2  = (const float*)d_in[4];
    const float* b2  = (const float*)d_in[5];
    const float* l1W = (const float*)d_in[6];
    const float* l1b = (const float*)d_in[7];
    const float* l2W = (const float*)d_in[8];
    const float* l2b = (const float*)d_in[9];
    float* out = (float*)d_out;

    int n = in_sizes[0] / FIN;
    int E = in_sizes[1] / 2;
    const int* row = ei;
    const int* col = ei + E;

    int *cnt, *off, *cur, *esrc, *bsum;
    float *dinv;
    __half2 *hl2, *h2, *ab2;
    __half *w1h, *w2h, *wabh;
    cudaGetSymbolAddress((void**)&cnt,  g_cnt);
    cudaGetSymbolAddress((void**)&off,  g_off);
    cudaGetSymbolAddress((void**)&cur,  g_cur);
    cudaGetSymbolAddress((void**)&esrc, g_esrc);
    cudaGetSymbolAddress((void**)&bsum, g_bsum);
    cudaGetSymbolAddress((void**)&dinv, g_dinv);
    cudaGetSymbolAddress((void**)&hl2,  g_hl2);
    cudaGetSymbolAddress((void**)&h2,   g_h2);
    cudaGetSymbolAddress((void**)&ab2,  g_ab2);
    cudaGetSymbolAddress((void**)&w1h,  g_w1h);
    cudaGetSymbolAddress((void**)&w2h,  g_w2h);
    cudaGetSymbolAddress((void**)&wabh, g_wabh);

    const int T = 256;
    int NB = (n + 255) / 256;

    // fork: CSR build + weight conversions on side stream; gemm1 path on main
    zero_cnt<<<NB, T>>>(cnt, n);
    cudaEventRecord(g_evFork, 0);
    cudaStreamWaitEvent(g_s2, g_evFork, 0);
    count_in<<<(E + T - 1) / T, T, 0, g_s2>>>(col, cnt, E);
    scan1<<<NB, T, 0, g_s2>>>(cnt, off, bsum, dinv, n);
    scan2<<<1, 512, 0, g_s2>>>(bsum, NB);
    scan3<<<NB, T, 0, g_s2>>>(off, bsum, cur, n, E);
    fill_csr<<<(E + T - 1) / T, T, 0, g_s2>>>(row, col, cur, esrc, E);
    conv_w<<<(HIDD * HIDD + T - 1) / T, T, 0, g_s2>>>(W2, w2h, HIDD * HIDD);
    repack_wab_h<<<(64 * 128 + T - 1) / T, T, 0, g_s2>>>(l1W, wabh);
    cudaEventRecord(g_evJoin, g_s2);

    conv_w<<<(FIN * HIDD + T - 1) / T, T>>>(W1, w1h, FIN * HIDD);
    gemm_mma<128, 64, false, false><<<(n + 63) / 64, 128>>>(x, w1h, nullptr, hl2, n);
    cudaStreamWaitEvent(0, g_evJoin, 0);

    gather_agg<true><<<(n * 8 + T - 1) / T, T>>>(off, esrc, hl2, dinv, b1, h2, n);

    gemm_mma<64, 64, true, true><<<(n + 63) / 64, 128>>>(h2, w2h, dinv, hl2, n);
    gather_agg<false><<<(n * 8 + T - 1) / T, T>>>(off, esrc, hl2, dinv, b2, h2, n);

    gemm_mma<64, 128, false, true><<<(n + 63) / 64, 128>>>(h2, wabh, nullptr, ab2, n);
    edge_mlp<<<(E * 8 + T - 1) / T, T>>>(row, col, ab2, l1b, l2W, l2b, out, E);
}

// round 10
// speedup vs baseline: 1.3660x; 1.0257x over previous
#include <cuda_runtime.h>
#include <cuda_fp16.h>

#define NMAX 100000
#define EMAX 1600000
#define HIDD 64
#define FIN  128

__device__ int     g_cnt[NMAX];
__device__ int     g_off[NMAX + 1];
__device__ int     g_cur[NMAX];
__device__ int     g_esrc[EMAX];
__device__ int     g_bsum[512];
__device__ float   g_dinv[NMAX];
__device__ __half2 g_hl2[NMAX * HIDD / 2];   // fp16, PRE-SCALED by dinv[src]
__device__ __half2 g_h2 [NMAX * HIDD / 2];   // fp16 aggregated features
__device__ __half2 g_ab2[NMAX * HIDD];       // fp16 [A|B] table
__device__ __half  g_w1h[FIN * HIDD];
__device__ __half  g_w2h[HIDD * HIDD];
__device__ __half  g_wabh[HIDD * 2 * HIDD];

static cudaStream_t g_s2;
static cudaEvent_t g_evFork, g_evDinv, g_evJoin;
namespace { struct StreamInit {
    StreamInit() {
        cudaStreamCreateWithFlags(&g_s2, cudaStreamNonBlocking);
        cudaEventCreateWithFlags(&g_evFork, cudaEventDisableTiming);
        cudaEventCreateWithFlags(&g_evDinv, cudaEventDisableTiming);
        cudaEventCreateWithFlags(&g_evJoin, cudaEventDisableTiming);
    }
} g_streamInit; }

// ---------------- CSC build ----------------
__global__ void count_in(const int* __restrict__ col, int* __restrict__ cnt, int E) {
    int e = blockIdx.x * blockDim.x + threadIdx.x;
    if (e < E) atomicAdd(&cnt[col[e]], 1);
}
__global__ void scan1(const int* __restrict__ cnt, int* __restrict__ off,
                      int* __restrict__ bsum, float* __restrict__ dinv, int n) {
    __shared__ int s[256];
    int tid = threadIdx.x;
    int i = blockIdx.x * 256 + tid;
    int v = (i < n) ? cnt[i] : 0;
    if (i < n) dinv[i] = rsqrtf((float)v + 1.0f);
    s[tid] = v;
    __syncthreads();
#pragma unroll
    for (int d = 1; d < 256; d <<= 1) {
        int t = (tid >= d) ? s[tid - d] : 0;
        __syncthreads();
        s[tid] += t;
        __syncthreads();
    }
    if (i < n) off[i] = s[tid] - v;
    if (tid == 255) bsum[blockIdx.x] = s[255];
}
__global__ void scan2(int* __restrict__ bsum, int nb) {
    __shared__ int s[512];
    int tid = threadIdx.x;
    int v = (tid < nb) ? bsum[tid] : 0;
    s[tid] = v;
    __syncthreads();
#pragma unroll
    for (int d = 1; d < 512; d <<= 1) {
        int t = (tid >= d) ? s[tid - d] : 0;
        __syncthreads();
        s[tid] += t;
        __syncthreads();
    }
    if (tid < nb) bsum[tid] = s[tid] - v;
}
__global__ void scan3(int* __restrict__ off, const int* __restrict__ bsum,
                      int* __restrict__ cur, int n, int E) {
    int i = blockIdx.x * 256 + threadIdx.x;
    if (i < n) {
        int o = off[i] + bsum[blockIdx.x];
        off[i] = o;
        cur[i] = o;
    }
    if (i == 0) off[n] = E;
}
__global__ void fill_csr(const int* __restrict__ row, const int* __restrict__ col,
                         int* __restrict__ cur, int* __restrict__ esrc, int E) {
    int e = blockIdx.x * blockDim.x + threadIdx.x;
    if (e < E) {
        int p = atomicAdd(&cur[col[e]], 1);
        esrc[p] = row[e];
    }
}

// ---------------- weight conversion ----------------
__global__ void conv_w(const float* __restrict__ src, __half* __restrict__ dst, int count) {
    int i = blockIdx.x * blockDim.x + threadIdx.x;
    if (i < count) dst[i] = __float2half_rn(src[i]);
}
__global__ void repack_wab_h(const float* __restrict__ l1W, __half* __restrict__ wabh) {
    int i = blockIdx.x * blockDim.x + threadIdx.x;
    if (i < 64 * 128) {
        int k = i >> 7, nn = i & 127;
        float v = (nn < 64) ? l1W[k * 64 + nn] : l1W[(64 + k) * 64 + (nn - 64)];
        wabh[i] = __float2half_rn(v);
    }
}

// ---------------- HMMA GEMM ----------------
template <int K, int N, bool SCALE, bool HALF_IN>
__global__ void gemm_mma(const void* __restrict__ Xv, const __half* __restrict__ Wh,
                         const float* __restrict__ dinv, __half2* __restrict__ Y, int nrows) {
    constexpr int XP = K + 8;
    constexpr int WP = N + 8;
    __shared__ __half Xs[64 * XP];
    __shared__ __half Ws[K * WP];
    int tid = threadIdx.x;
    int warp = tid >> 5, lane = tid & 31;
    int row0 = blockIdx.x * 64;

    if (HALF_IN) {
        const __half* X = (const __half*)Xv;
        for (int j = tid; j < 64 * (K / 8); j += 128) {
            int r = j / (K / 8), kq = j % (K / 8);
            int gr = row0 + r;
            uint4 u = make_uint4(0, 0, 0, 0);
            if (gr < nrows) u = *reinterpret_cast<const uint4*>(&X[(size_t)gr * K + kq * 8]);
            *reinterpret_cast<uint4*>(&Xs[r * XP + kq * 8]) = u;
        }
    } else {
        const float* X = (const float*)Xv;
        for (int j = tid; j < 64 * (K / 4); j += 128) {
            int r = j / (K / 4), kq = j % (K / 4);
            int gr = row0 + r;
            float4 v = (gr < nrows)
                ? *reinterpret_cast<const float4*>(&X[(size_t)gr * K + kq * 4])
                : make_float4(0.f, 0.f, 0.f, 0.f);
            __half2 h0 = __floats2half2_rn(v.x, v.y);
            __half2 h1 = __floats2half2_rn(v.z, v.w);
            uint2 u;
            u.x = *reinterpret_cast<unsigned*>(&h0);
            u.y = *reinterpret_cast<unsigned*>(&h1);
            *reinterpret_cast<uint2*>(&Xs[r * XP + kq * 4]) = u;
        }
    }
    for (int j = tid; j < K * (N / 8); j += 128) {
        int k = j / (N / 8), nq = j % (N / 8);
        *reinterpret_cast<uint4*>(&Ws[k * WP + nq * 8]) =
            *reinterpret_cast<const uint4*>(&Wh[(size_t)k * N + nq * 8]);
    }
    __syncthreads();

    float acc[N / 8][4];
#pragma unroll
    for (int nt = 0; nt < N / 8; nt++)
#pragma unroll
        for (int q = 0; q < 4; q++) acc[nt][q] = 0.f;

    int arow = warp * 16 + (lane & 15);
    int acol = (lane >> 4) * 8;
    int brow_l = lane & 15;

#pragma unroll
    for (int kt = 0; kt < K / 16; kt++) {
        unsigned a0, a1, a2, a3;
        unsigned aaddr = (unsigned)__cvta_generic_to_shared(&Xs[arow * XP + kt * 16 + acol]);
        asm volatile("ldmatrix.sync.aligned.m8n8.x4.shared.b16 {%0,%1,%2,%3}, [%4];"
                     : "=r"(a0), "=r"(a1), "=r"(a2), "=r"(a3) : "r"(aaddr));
#pragma unroll
        for (int nt = 0; nt < N / 8; nt++) {
            unsigned b0, b1;
            unsigned baddr = (unsigned)__cvta_generic_to_shared(
                &Ws[(kt * 16 + brow_l) * WP + nt * 8]);
            asm volatile("ldmatrix.sync.aligned.m8n8.x2.trans.shared.b16 {%0,%1}, [%2];"
                         : "=r"(b0), "=r"(b1) : "r"(baddr));
            asm volatile(
                "mma.sync.aligned.m16n8k16.row.col.f32.f16.f16.f32 "
                "{%0,%1,%2,%3}, {%4,%5,%6,%7}, {%8,%9}, {%0,%1,%2,%3};"
                : "+f"(acc[nt][0]), "+f"(acc[nt][1]), "+f"(acc[nt][2]), "+f"(acc[nt][3])
                : "r"(a0), "r"(a1), "r"(a2), "r"(a3), "r"(b0), "r"(b1));
        }
    }

    int rr = warp * 16 + (lane >> 2);
    int cq = lane & 3;
#pragma unroll
    for (int hh = 0; hh < 2; hh++) {
        int gr = row0 + rr + hh * 8;
        if (gr < nrows) {
            float s = SCALE ? dinv[gr] : 1.0f;
#pragma unroll
            for (int nt = 0; nt < N / 8; nt++) {
                __half2 p = __floats2half2_rn(acc[nt][hh * 2 + 0] * s,
                                              acc[nt][hh * 2 + 1] * s);
                Y[(size_t)gr * (N / 2) + nt * 4 + cq] = p;
            }
        }
    }
}

__device__ __forceinline__ __half2 as_h2(unsigned u) { return *reinterpret_cast<__half2*>(&u); }

__device__ __forceinline__ void acc_f32_u4(float4& a, float4& b, uint4 u) {
    float2 f0 = __half22float2(as_h2(u.x));
    float2 f1 = __half22float2(as_h2(u.y));
    float2 f2 = __half22float2(as_h2(u.z));
    float2 f3 = __half22float2(as_h2(u.w));
    a.x += f0.x; a.y += f0.y; a.z += f1.x; a.w += f1.y;
    b.x += f2.x; b.y += f2.y; b.z += f3.x; b.w += f3.y;
}
// pairwise fp16 add, then fp32 accumulate
__device__ __forceinline__ void acc_pair_u4(float4& a, float4& b, uint4 u0, uint4 u1) {
    __half2 p0 = __hadd2(as_h2(u0.x), as_h2(u1.x));
    __half2 p1 = __hadd2(as_h2(u0.y), as_h2(u1.y));
    __half2 p2 = __hadd2(as_h2(u0.z), as_h2(u1.z));
    __half2 p3 = __hadd2(as_h2(u0.w), as_h2(u1.w));
    float2 f0 = __half22float2(p0);
    float2 f1 = __half22float2(p1);
    float2 f2 = __half22float2(p2);
    float2 f3 = __half22float2(p3);
    a.x += f0.x; a.y += f0.y; a.z += f1.x; a.w += f1.y;
    b.x += f2.x; b.y += f2.y; b.z += f3.x; b.w += f3.y;
}

// ---------------- aggregation: sources pre-scaled; 8 lanes/node, uint4/lane ----------------
__global__ void gather_agg(const int* __restrict__ off, const int* __restrict__ esrc,
                           const __half2* __restrict__ hls, const float* __restrict__ dinv,
                           const float* __restrict__ bias, __half2* __restrict__ h, int n) {
    __shared__ float sb[64];
    if (threadIdx.x < 64) sb[threadIdx.x] = bias[threadIdx.x];
    __syncthreads();
    int gid = blockIdx.x * 256 + threadIdx.x;
    int c = gid >> 3;
    if (c >= n) return;
    int l = gid & 7;
    const uint4* hp = reinterpret_cast<const uint4*>(hls);
    float dc = dinv[c];
    float4 a = make_float4(0.f, 0.f, 0.f, 0.f);
    float4 b = make_float4(0.f, 0.f, 0.f, 0.f);
    acc_f32_u4(a, b, hp[(size_t)c * 8 + l]);  // self (pre-scaled)
    int s = off[c], e2 = off[c + 1];
    int j = s;
    for (; j + 3 < e2; j += 4) {
        int r0 = esrc[j], r1 = esrc[j + 1], r2 = esrc[j + 2], r3 = esrc[j + 3];
        uint4 u0 = hp[(size_t)r0 * 8 + l];
        uint4 u1 = hp[(size_t)r1 * 8 + l];
        uint4 u2 = hp[(size_t)r2 * 8 + l];
        uint4 u3 = hp[(size_t)r3 * 8 + l];
        acc_pair_u4(a, b, u0, u1);
        acc_pair_u4(a, b, u2, u3);
    }
    for (; j + 1 < e2; j += 2) {
        int r0 = esrc[j], r1 = esrc[j + 1];
        uint4 u0 = hp[(size_t)r0 * 8 + l];
        uint4 u1 = hp[(size_t)r1 * 8 + l];
        acc_pair_u4(a, b, u0, u1);
    }
    if (j < e2) acc_f32_u4(a, b, hp[(size_t)esrc[j] * 8 + l]);
    int jb = l * 8;
    __half2 p0 = __floats2half2_rn(fmaxf(a.x * dc + sb[jb + 0], 0.f), fmaxf(a.y * dc + sb[jb + 1], 0.f));
    __half2 p1 = __floats2half2_rn(fmaxf(a.z * dc + sb[jb + 2], 0.f), fmaxf(a.w * dc + sb[jb + 3], 0.f));
    __half2 p2 = __floats2half2_rn(fmaxf(b.x * dc + sb[jb + 4], 0.f), fmaxf(b.y * dc + sb[jb + 5], 0.f));
    __half2 p3 = __floats2half2_rn(fmaxf(b.z * dc + sb[jb + 6], 0.f), fmaxf(b.w * dc + sb[jb + 7], 0.f));
    uint4 o;
    o.x = *reinterpret_cast<unsigned*>(&p0);
    o.y = *reinterpret_cast<unsigned*>(&p1);
    o.z = *reinterpret_cast<unsigned*>(&p2);
    o.w = *reinterpret_cast<unsigned*>(&p3);
    reinterpret_cast<uint4*>(h)[(size_t)c * 8 + l] = o;
}

// ---------------- edge MLP: fp16 z-build, fp32 dot. 8 lanes/edge ----------------
__global__ void edge_mlp(const int* __restrict__ row, const int* __restrict__ col,
                         const __half2* __restrict__ ab, const float* __restrict__ l1b,
                         const float* __restrict__ l2w, const float* __restrict__ l2b,
                         float* __restrict__ out, int E) {
    __shared__ __half2 s1bh[32];
    __shared__ float s2w[128], s2b[2];
    int tid = threadIdx.x;
    if (tid < 32)        s1bh[tid] = __floats2half2_rn(l1b[tid * 2], l1b[tid * 2 + 1]);
    else if (tid < 160)  s2w[tid - 32]  = l2w[tid - 32];
    else if (tid < 162)  s2b[tid - 160] = l2b[tid - 160];
    __syncthreads();
    int gid = blockIdx.x * 256 + tid;
    int e = gid >> 3;
    if (e >= E) return;
    int l = gid & 7;
    int r = row[e], c = col[e];
    const uint4* ap = reinterpret_cast<const uint4*>(ab);
    uint4 ua = ap[(size_t)r * 16 + l];
    uint4 ub = ap[(size_t)c * 16 + 8 + l];
    const __half2 hz = __float2half2_rn(0.f);
    __half2 z0 = __hmax2(__hadd2(__hadd2(as_h2(ua.x), as_h2(ub.x)), s1bh[l * 4 + 0]), hz);
    __half2 z1 = __hmax2(__hadd2(__hadd2(as_h2(ua.y), as_h2(ub.y)), s1bh[l * 4 + 1]), hz);
    __half2 z2 = __hmax2(__hadd2(__hadd2(as_h2(ua.z), as_h2(ub.z)), s1bh[l * 4 + 2]), hz);
    __half2 z3 = __hmax2(__hadd2(__hadd2(as_h2(ua.w), as_h2(ub.w)), s1bh[l * 4 + 3]), hz);
    float2 f0 = __half22float2(z0);
    float2 f1 = __half22float2(z1);
    float2 f2 = __half22float2(z2);
    float2 f3 = __half22float2(z3);
    int j = l * 8;
    float s0, s1;
    s0  = f0.x * s2w[(j + 0) * 2];     s1  = f0.x * s2w[(j + 0) * 2 + 1];
    s0 += f0.y * s2w[(j + 1) * 2];     s1 += f0.y * s2w[(j + 1) * 2 + 1];
    s0 += f1.x * s2w[(j + 2) * 2];     s1 += f1.x * s2w[(j + 2) * 2 + 1];
    s0 += f1.y * s2w[(j + 3) * 2];     s1 += f1.y * s2w[(j + 3) * 2 + 1];
    s0 += f2.x * s2w[(j + 4) * 2];     s1 += f2.x * s2w[(j + 4) * 2 + 1];
    s0 += f2.y * s2w[(j + 5) * 2];     s1 += f2.y * s2w[(j + 5) * 2 + 1];
    s0 += f3.x * s2w[(j + 6) * 2];     s1 += f3.x * s2w[(j + 6) * 2 + 1];
    s0 += f3.y * s2w[(j + 7) * 2];     s1 += f3.y * s2w[(j + 7) * 2 + 1];
#pragma unroll
    for (int off = 4; off > 0; off >>= 1) {
        s0 += __shfl_down_sync(0xFFFFFFFFu, s0, off, 8);
        s1 += __shfl_down_sync(0xFFFFFFFFu, s1, off, 8);
    }
    if (l == 0) {
        s0 += s2b[0]; s1 += s2b[1];
        float m = fmaxf(s0, s1);
        float lse = m + logf(expf(s0 - m) + expf(s1 - m));
        float2 o = make_float2(s0 - lse, s1 - lse);
        *reinterpret_cast<float2*>(&out[2 * (size_t)e]) = o;
    }
}

extern "C" void kernel_launch(void* const* d_in, const int* in_sizes, int n_in,
                              void* d_out, int out_size) {
    const float* x   = (const float*)d_in[0];
    const int*   ei  = (const int*)d_in[1];
    const float* W1  = (const float*)d_in[2];
    const float* b1  = (const float*)d_in[3];
    const float* W2  = (const float*)d_in[4];
    const float* b2  = (const float*)d_in[5];
    const float* l1W = (const float*)d_in[6];
    const float* l1b = (const float*)d_in[7];
    const float* l2W = (const float*)d_in[8];
    const float* l2b = (const float*)d_in[9];
    float* out = (float*)d_out;

    int n = in_sizes[0] / FIN;
    int E = in_sizes[1] / 2;
    const int* row = ei;
    const int* col = ei + E;

    int *cnt, *off, *cur, *esrc, *bsum;
    float *dinv;
    __half2 *hl2, *h2, *ab2;
    __half *w1h, *w2h, *wabh;
    cudaGetSymbolAddress((void**)&cnt,  g_cnt);
    cudaGetSymbolAddress((void**)&off,  g_off);
    cudaGetSymbolAddress((void**)&cur,  g_cur);
    cudaGetSymbolAddress((void**)&esrc, g_esrc);
    cudaGetSymbolAddress((void**)&bsum, g_bsum);
    cudaGetSymbolAddress((void**)&dinv, g_dinv);
    cudaGetSymbolAddress((void**)&hl2,  g_hl2);
    cudaGetSymbolAddress((void**)&h2,   g_h2);
    cudaGetSymbolAddress((void**)&ab2,  g_ab2);
    cudaGetSymbolAddress((void**)&w1h,  g_w1h);
    cudaGetSymbolAddress((void**)&w2h,  g_w2h);
    cudaGetSymbolAddress((void**)&wabh, g_wabh);

    const int T = 256;
    int NB = (n + 255) / 256;

    // fork: CSR build + weight conversions on side stream
    cudaMemsetAsync(cnt, 0, (size_t)n * sizeof(int), 0);
    cudaEventRecord(g_evFork, 0);
    cudaStreamWaitEvent(g_s2, g_evFork, 0);
    count_in<<<(E + T - 1) / T, T, 0, g_s2>>>(col, cnt, E);
    scan1<<<NB, T, 0, g_s2>>>(cnt, off, bsum, dinv, n);
    cudaEventRecord(g_evDinv, g_s2);          // dinv ready early
    scan2<<<1, 512, 0, g_s2>>>(bsum, NB);
    scan3<<<NB, T, 0, g_s2>>>(off, bsum, cur, n, E);
    fill_csr<<<(E + T - 1) / T, T, 0, g_s2>>>(row, col, cur, esrc, E);
    conv_w<<<(HIDD * HIDD + T - 1) / T, T, 0, g_s2>>>(W2, w2h, HIDD * HIDD);
    repack_wab_h<<<(64 * 128 + T - 1) / T, T, 0, g_s2>>>(l1W, wabh);
    cudaEventRecord(g_evJoin, g_s2);

    // main: W1 conversion overlaps count_in; gemm1 (scaled) waits only for dinv
    conv_w<<<(FIN * HIDD + T - 1) / T, T>>>(W1, w1h, FIN * HIDD);
    cudaStreamWaitEvent(0, g_evDinv, 0);
    gemm_mma<128, 64, true, false><<<(n + 63) / 64, 128>>>(x, w1h, dinv, hl2, n);
    cudaStreamWaitEvent(0, g_evJoin, 0);

    gather_agg<<<(n * 8 + T - 1) / T, T>>>(off, esrc, hl2, dinv, b1, h2, n);

    gemm_mma<64, 64, true, true><<<(n + 63) / 64, 128>>>(h2, w2h, dinv, hl2, n);
    gather_agg<<<(n * 8 + T - 1) / T, T>>>(off, esrc, hl2, dinv, b2, h2, n);

    gemm_mma<64, 128, false, true><<<(n + 63) / 64, 128>>>(h2, wabh, nullptr, ab2, n);
    edge_mlp<<<(E * 8 + T - 1) / T, T>>>(row, col, ab2, l1b, l2W, l2b, out, E);
}

// round 11
// speedup vs baseline: 1.3674x; 1.0010x over previous
#include <cuda_runtime.h>
#include <cuda_fp16.h>

#define NMAX 100000
#define EMAX 1600000
#define HIDD 64
#define FIN  128

__device__ int     g_cnt[NMAX];
__device__ int     g_off[NMAX + 1];
__device__ int     g_cur[NMAX];
__device__ int     g_esrc[EMAX];
__device__ int     g_eidx[EMAX];
__device__ int     g_bsum[512];
__device__ float   g_dinv[NMAX];
__device__ __half2 g_hl2[NMAX * HIDD / 2];   // fp16, PRE-SCALED by dinv[src]
__device__ __half2 g_h2 [NMAX * HIDD / 2];   // fp16 aggregated features
__device__ __half2 g_ab2[NMAX * HIDD];       // fp16 [A|B] table
__device__ __half  g_w1h[FIN * HIDD];
__device__ __half  g_w2h[HIDD * HIDD];
__device__ __half  g_wabh[HIDD * 2 * HIDD];

static cudaStream_t g_s2;
static cudaEvent_t g_evFork, g_evDinv, g_evJoin;
namespace { struct StreamInit {
    StreamInit() {
        cudaStreamCreateWithFlags(&g_s2, cudaStreamNonBlocking);
        cudaEventCreateWithFlags(&g_evFork, cudaEventDisableTiming);
        cudaEventCreateWithFlags(&g_evDinv, cudaEventDisableTiming);
        cudaEventCreateWithFlags(&g_evJoin, cudaEventDisableTiming);
    }
} g_streamInit; }

// ---------------- CSC build ----------------
__global__ void count_in(const int* __restrict__ col, int* __restrict__ cnt, int E) {
    int e = blockIdx.x * blockDim.x + threadIdx.x;
    if (e < E) atomicAdd(&cnt[col[e]], 1);
}
__global__ void scan1(const int* __restrict__ cnt, int* __restrict__ off,
                      int* __restrict__ bsum, float* __restrict__ dinv, int n) {
    __shared__ int s[256];
    int tid = threadIdx.x;
    int i = blockIdx.x * 256 + tid;
    int v = (i < n) ? cnt[i] : 0;
    if (i < n) dinv[i] = rsqrtf((float)v + 1.0f);
    s[tid] = v;
    __syncthreads();
#pragma unroll
    for (int d = 1; d < 256; d <<= 1) {
        int t = (tid >= d) ? s[tid - d] : 0;
        __syncthreads();
        s[tid] += t;
        __syncthreads();
    }
    if (i < n) off[i] = s[tid] - v;
    if (tid == 255) bsum[blockIdx.x] = s[255];
}
__global__ void scan2(int* __restrict__ bsum, int nb) {
    __shared__ int s[512];
    int tid = threadIdx.x;
    int v = (tid < nb) ? bsum[tid] : 0;
    s[tid] = v;
    __syncthreads();
#pragma unroll
    for (int d = 1; d < 512; d <<= 1) {
        int t = (tid >= d) ? s[tid - d] : 0;
        __syncthreads();
        s[tid] += t;
        __syncthreads();
    }
    if (tid < nb) bsum[tid] = s[tid] - v;
}
__global__ void scan3(int* __restrict__ off, const int* __restrict__ bsum,
                      int* __restrict__ cur, int n, int E) {
    int i = blockIdx.x * 256 + threadIdx.x;
    if (i < n) {
        int o = off[i] + bsum[blockIdx.x];
        off[i] = o;
        cur[i] = o;
    }
    if (i == 0) off[n] = E;
}
__global__ void fill_csr(const int* __restrict__ row, const int* __restrict__ col,
                         int* __restrict__ cur, int* __restrict__ esrc,
                         int* __restrict__ eidx, int E) {
    int e = blockIdx.x * blockDim.x + threadIdx.x;
    if (e < E) {
        int p = atomicAdd(&cur[col[e]], 1);
        esrc[p] = row[e];
        eidx[p] = e;
    }
}

// ---------------- weight conversion ----------------
__global__ void conv_w(const float* __restrict__ src, __half* __restrict__ dst, int count) {
    int i = blockIdx.x * blockDim.x + threadIdx.x;
    if (i < count) dst[i] = __float2half_rn(src[i]);
}
__global__ void repack_wab_h(const float* __restrict__ l1W, __half* __restrict__ wabh) {
    int i = blockIdx.x * blockDim.x + threadIdx.x;
    if (i < 64 * 128) {
        int k = i >> 7, nn = i & 127;
        float v = (nn < 64) ? l1W[k * 64 + nn] : l1W[(64 + k) * 64 + (nn - 64)];
        wabh[i] = __float2half_rn(v);
    }
}

// ---------------- HMMA GEMM ----------------
template <int K, int N, bool SCALE, bool HALF_IN>
__global__ void gemm_mma(const void* __restrict__ Xv, const __half* __restrict__ Wh,
                         const float* __restrict__ dinv, __half2* __restrict__ Y, int nrows) {
    constexpr int XP = K + 8;
    constexpr int WP = N + 8;
    __shared__ __half Xs[64 * XP];
    __shared__ __half Ws[K * WP];
    int tid = threadIdx.x;
    int warp = tid >> 5, lane = tid & 31;
    int row0 = blockIdx.x * 64;

    if (HALF_IN) {
        const __half* X = (const __half*)Xv;
        for (int j = tid; j < 64 * (K / 8); j += 128) {
            int r = j / (K / 8), kq = j % (K / 8);
            int gr = row0 + r;
            uint4 u = make_uint4(0, 0, 0, 0);
            if (gr < nrows) u = *reinterpret_cast<const uint4*>(&X[(size_t)gr * K + kq * 8]);
            *reinterpret_cast<uint4*>(&Xs[r * XP + kq * 8]) = u;
        }
    } else {
        const float* X = (const float*)Xv;
        for (int j = tid; j < 64 * (K / 4); j += 128) {
            int r = j / (K / 4), kq = j % (K / 4);
            int gr = row0 + r;
            float4 v = (gr < nrows)
                ? *reinterpret_cast<const float4*>(&X[(size_t)gr * K + kq * 4])
                : make_float4(0.f, 0.f, 0.f, 0.f);
            __half2 h0 = __floats2half2_rn(v.x, v.y);
            __half2 h1 = __floats2half2_rn(v.z, v.w);
            uint2 u;
            u.x = *reinterpret_cast<unsigned*>(&h0);
            u.y = *reinterpret_cast<unsigned*>(&h1);
            *reinterpret_cast<uint2*>(&Xs[r * XP + kq * 4]) = u;
        }
    }
    for (int j = tid; j < K * (N / 8); j += 128) {
        int k = j / (N / 8), nq = j % (N / 8);
        *reinterpret_cast<uint4*>(&Ws[k * WP + nq * 8]) =
            *reinterpret_cast<const uint4*>(&Wh[(size_t)k * N + nq * 8]);
    }
    __syncthreads();

    float acc[N / 8][4];
#pragma unroll
    for (int nt = 0; nt < N / 8; nt++)
#pragma unroll
        for (int q = 0; q < 4; q++) acc[nt][q] = 0.f;

    int arow = warp * 16 + (lane & 15);
    int acol = (lane >> 4) * 8;
    int brow_l = lane & 15;

#pragma unroll
    for (int kt = 0; kt < K / 16; kt++) {
        unsigned a0, a1, a2, a3;
        unsigned aaddr = (unsigned)__cvta_generic_to_shared(&Xs[arow * XP + kt * 16 + acol]);
        asm volatile("ldmatrix.sync.aligned.m8n8.x4.shared.b16 {%0,%1,%2,%3}, [%4];"
                     : "=r"(a0), "=r"(a1), "=r"(a2), "=r"(a3) : "r"(aaddr));
#pragma unroll
        for (int nt = 0; nt < N / 8; nt++) {
            unsigned b0, b1;
            unsigned baddr = (unsigned)__cvta_generic_to_shared(
                &Ws[(kt * 16 + brow_l) * WP + nt * 8]);
            asm volatile("ldmatrix.sync.aligned.m8n8.x2.trans.shared.b16 {%0,%1}, [%2];"
                         : "=r"(b0), "=r"(b1) : "r"(baddr));
            asm volatile(
                "mma.sync.aligned.m16n8k16.row.col.f32.f16.f16.f32 "
                "{%0,%1,%2,%3}, {%4,%5,%6,%7}, {%8,%9}, {%0,%1,%2,%3};"
                : "+f"(acc[nt][0]), "+f"(acc[nt][1]), "+f"(acc[nt][2]), "+f"(acc[nt][3])
                : "r"(a0), "r"(a1), "r"(a2), "r"(a3), "r"(b0), "r"(b1));
        }
    }

    int rr = warp * 16 + (lane >> 2);
    int cq = lane & 3;
#pragma unroll
    for (int hh = 0; hh < 2; hh++) {
        int gr = row0 + rr + hh * 8;
        if (gr < nrows) {
            float s = SCALE ? dinv[gr] : 1.0f;
#pragma unroll
            for (int nt = 0; nt < N / 8; nt++) {
                __half2 p = __floats2half2_rn(acc[nt][hh * 2 + 0] * s,
                                              acc[nt][hh * 2 + 1] * s);
                Y[(size_t)gr * (N / 2) + nt * 4 + cq] = p;
            }
        }
    }
}

__device__ __forceinline__ __half2 as_h2(unsigned u) { return *reinterpret_cast<__half2*>(&u); }

__device__ __forceinline__ void acc_f32_u4(float4& a, float4& b, uint4 u) {
    float2 f0 = __half22float2(as_h2(u.x));
    float2 f1 = __half22float2(as_h2(u.y));
    float2 f2 = __half22float2(as_h2(u.z));
    float2 f3 = __half22float2(as_h2(u.w));
    a.x += f0.x; a.y += f0.y; a.z += f1.x; a.w += f1.y;
    b.x += f2.x; b.y += f2.y; b.z += f3.x; b.w += f3.y;
}
__device__ __forceinline__ void acc_pair_u4(float4& a, float4& b, uint4 u0, uint4 u1) {
    __half2 p0 = __hadd2(as_h2(u0.x), as_h2(u1.x));
    __half2 p1 = __hadd2(as_h2(u0.y), as_h2(u1.y));
    __half2 p2 = __hadd2(as_h2(u0.z), as_h2(u1.z));
    __half2 p3 = __hadd2(as_h2(u0.w), as_h2(u1.w));
    float2 f0 = __half22float2(p0);
    float2 f1 = __half22float2(p1);
    float2 f2 = __half22float2(p2);
    float2 f3 = __half22float2(p3);
    a.x += f0.x; a.y += f0.y; a.z += f1.x; a.w += f1.y;
    b.x += f2.x; b.y += f2.y; b.z += f3.x; b.w += f3.y;
}

// ---------------- aggregation: sources pre-scaled; 8 lanes/node ----------------
__global__ void gather_agg(const int* __restrict__ off, const int* __restrict__ esrc,
                           const __half2* __restrict__ hls, const float* __restrict__ dinv,
                           const float* __restrict__ bias, __half2* __restrict__ h, int n) {
    __shared__ float sb[64];
    if (threadIdx.x < 64) sb[threadIdx.x] = bias[threadIdx.x];
    __syncthreads();
    int gid = blockIdx.x * 256 + threadIdx.x;
    int c = gid >> 3;
    if (c >= n) return;
    int l = gid & 7;
    const uint4* hp = reinterpret_cast<const uint4*>(hls);
    float dc = dinv[c];
    float4 a = make_float4(0.f, 0.f, 0.f, 0.f);
    float4 b = make_float4(0.f, 0.f, 0.f, 0.f);
    acc_f32_u4(a, b, hp[(size_t)c * 8 + l]);  // self (pre-scaled)
    int s = off[c], e2 = off[c + 1];
    int j = s;
    for (; j + 3 < e2; j += 4) {
        int r0 = esrc[j], r1 = esrc[j + 1], r2 = esrc[j + 2], r3 = esrc[j + 3];
        uint4 u0 = hp[(size_t)r0 * 8 + l];
        uint4 u1 = hp[(size_t)r1 * 8 + l];
        uint4 u2 = hp[(size_t)r2 * 8 + l];
        uint4 u3 = hp[(size_t)r3 * 8 + l];
        acc_pair_u4(a, b, u0, u1);
        acc_pair_u4(a, b, u2, u3);
    }
    for (; j + 1 < e2; j += 2) {
        int r0 = esrc[j], r1 = esrc[j + 1];
        uint4 u0 = hp[(size_t)r0 * 8 + l];
        uint4 u1 = hp[(size_t)r1 * 8 + l];
        acc_pair_u4(a, b, u0, u1);
    }
    if (j < e2) acc_f32_u4(a, b, hp[(size_t)esrc[j] * 8 + l]);
    int jb = l * 8;
    __half2 p0 = __floats2half2_rn(fmaxf(a.x * dc + sb[jb + 0], 0.f), fmaxf(a.y * dc + sb[jb + 1], 0.f));
    __half2 p1 = __floats2half2_rn(fmaxf(a.z * dc + sb[jb + 2], 0.f), fmaxf(a.w * dc + sb[jb + 3], 0.f));
    __half2 p2 = __floats2half2_rn(fmaxf(b.x * dc + sb[jb + 4], 0.f), fmaxf(b.y * dc + sb[jb + 5], 0.f));
    __half2 p3 = __floats2half2_rn(fmaxf(b.z * dc + sb[jb + 6], 0.f), fmaxf(b.w * dc + sb[jb + 7], 0.f));
    uint4 o;
    o.x = *reinterpret_cast<unsigned*>(&p0);
    o.y = *reinterpret_cast<unsigned*>(&p1);
    o.z = *reinterpret_cast<unsigned*>(&p2);
    o.w = *reinterpret_cast<unsigned*>(&p3);
    reinterpret_cast<uint4*>(h)[(size_t)c * 8 + l] = o;
}

// ---------------- edge MLP, CSC-ordered: 8 lanes per destination node ----------------
// B[c]+b1 loaded/folded once per node; per edge only A[src] is a random load.
// Two-class log-softmax via d = s0-s1: o0 = -softplus(-d), o1 = -softplus(d).
__global__ void edge_mlp_csc(const int* __restrict__ off, const int* __restrict__ esrc,
                             const int* __restrict__ eidx, const __half2* __restrict__ ab,
                             const float* __restrict__ l1b, const float* __restrict__ l2w,
                             const float* __restrict__ l2b, float* __restrict__ out, int n) {
    __shared__ __half2 s1bh[32];
    __shared__ float swd[64];
    __shared__ float sdb;
    int tid = threadIdx.x;
    if (tid < 32)       s1bh[tid] = __floats2half2_rn(l1b[tid * 2], l1b[tid * 2 + 1]);
    else if (tid < 96)  swd[tid - 32] = l2w[(tid - 32) * 2] - l2w[(tid - 32) * 2 + 1];
    else if (tid == 96) sdb = l2b[0] - l2b[1];
    __syncthreads();
    int gid = blockIdx.x * 256 + tid;
    int c = gid >> 3;
    if (c >= n) return;
    int l = gid & 7;
    const uint4* ap = reinterpret_cast<const uint4*>(ab);
    uint4 ub = ap[(size_t)c * 16 + 8 + l];
    // fold bias into B half-row
    __half2 hb0 = __hadd2(as_h2(ub.x), s1bh[l * 4 + 0]);
    __half2 hb1 = __hadd2(as_h2(ub.y), s1bh[l * 4 + 1]);
    __half2 hb2 = __hadd2(as_h2(ub.z), s1bh[l * 4 + 2]);
    __half2 hb3 = __hadd2(as_h2(ub.w), s1bh[l * 4 + 3]);
    const __half2 hz = __float2half2_rn(0.f);
    int j = l * 8;
    float w0 = swd[j + 0], w1 = swd[j + 1], w2 = swd[j + 2], w3 = swd[j + 3];
    float w4 = swd[j + 4], w5 = swd[j + 5], w6 = swd[j + 6], w7 = swd[j + 7];
    int s = off[c], e2 = off[c + 1];
    for (int p = s; p < e2; p++) {
        int r = esrc[p];
        uint4 ua = ap[(size_t)r * 16 + l];
        __half2 z0 = __hmax2(__hadd2(as_h2(ua.x), hb0), hz);
        __half2 z1 = __hmax2(__hadd2(as_h2(ua.y), hb1), hz);
        __half2 z2 = __hmax2(__hadd2(as_h2(ua.z), hb2), hz);
        __half2 z3 = __hmax2(__hadd2(as_h2(ua.w), hb3), hz);
        float2 f0 = __half22float2(z0);
        float2 f1 = __half22float2(z1);
        float2 f2 = __half22float2(z2);
        float2 f3 = __half22float2(z3);
        float d = f0.x * w0 + f0.y * w1 + f1.x * w2 + f1.y * w3
                + f2.x * w4 + f2.y * w5 + f3.x * w6 + f3.y * w7;
#pragma unroll
        for (int o = 4; o > 0; o >>= 1)
            d += __shfl_down_sync(0xFFFFFFFFu, d, o, 8);
        if (l == 0) {
            d += sdb;
            float ad = fabsf(d);
            float lp = log1pf(__expf(-ad));
            float o0 = (d > 0.f) ? -lp : (d - lp);
            float o1 = o0 - d;
            int e = eidx[p];
            *reinterpret_cast<float2*>(&out[2 * (size_t)e]) = make_float2(o0, o1);
        }
    }
}

extern "C" void kernel_launch(void* const* d_in, const int* in_sizes, int n_in,
                              void* d_out, int out_size) {
    const float* x   = (const float*)d_in[0];
    const int*   ei  = (const int*)d_in[1];
    const float* W1  = (const float*)d_in[2];
    const float* b1  = (const float*)d_in[3];
    const float* W2  = (const float*)d_in[4];
    const float* b2  = (const float*)d_in[5];
    const float* l1W = (const float*)d_in[6];
    const float* l1b = (const float*)d_in[7];
    const float* l2W = (const float*)d_in[8];
    const float* l2b = (const float*)d_in[9];
    float* out = (float*)d_out;

    int n = in_sizes[0] / FIN;
    int E = in_sizes[1] / 2;
    const int* row = ei;
    const int* col = ei + E;

    int *cnt, *off, *cur, *esrc, *eidx, *bsum;
    float *dinv;
    __half2 *hl2, *h2, *ab2;
    __half *w1h, *w2h, *wabh;
    cudaGetSymbolAddress((void**)&cnt,  g_cnt);
    cudaGetSymbolAddress((void**)&off,  g_off);
    cudaGetSymbolAddress((void**)&cur,  g_cur);
    cudaGetSymbolAddress((void**)&esrc, g_esrc);
    cudaGetSymbolAddress((void**)&eidx, g_eidx);
    cudaGetSymbolAddress((void**)&bsum, g_bsum);
    cudaGetSymbolAddress((void**)&dinv, g_dinv);
    cudaGetSymbolAddress((void**)&hl2,  g_hl2);
    cudaGetSymbolAddress((void**)&h2,   g_h2);
    cudaGetSymbolAddress((void**)&ab2,  g_ab2);
    cudaGetSymbolAddress((void**)&w1h,  g_w1h);
    cudaGetSymbolAddress((void**)&w2h,  g_w2h);
    cudaGetSymbolAddress((void**)&wabh, g_wabh);

    const int T = 256;
    int NB = (n + 255) / 256;

    // fork: CSR build + weight conversions on side stream
    cudaMemsetAsync(cnt, 0, (size_t)n * sizeof(int), 0);
    cudaEventRecord(g_evFork, 0);
    cudaStreamWaitEvent(g_s2, g_evFork, 0);
    count_in<<<(E + T - 1) / T, T, 0, g_s2>>>(col, cnt, E);
    scan1<<<NB, T, 0, g_s2>>>(cnt, off, bsum, dinv, n);
    cudaEventRecord(g_evDinv, g_s2);
    scan2<<<1, 512, 0, g_s2>>>(bsum, NB);
    scan3<<<NB, T, 0, g_s2>>>(off, bsum, cur, n, E);
    fill_csr<<<(E + T - 1) / T, T, 0, g_s2>>>(row, col, cur, esrc, eidx, E);
    conv_w<<<(HIDD * HIDD + T - 1) / T, T, 0, g_s2>>>(W2, w2h, HIDD * HIDD);
    repack_wab_h<<<(64 * 128 + T - 1) / T, T, 0, g_s2>>>(l1W, wabh);
    cudaEventRecord(g_evJoin, g_s2);

    // main: W1 conversion overlaps count_in; gemm1 (scaled) waits only for dinv
    conv_w<<<(FIN * HIDD + T - 1) / T, T>>>(W1, w1h, FIN * HIDD);
    cudaStreamWaitEvent(0, g_evDinv, 0);
    gemm_mma<128, 64, true, false><<<(n + 63) / 64, 128>>>(x, w1h, dinv, hl2, n);
    cudaStreamWaitEvent(0, g_evJoin, 0);

    gather_agg<<<(n * 8 + T - 1) / T, T>>>(off, esrc, hl2, dinv, b1, h2, n);

    gemm_mma<64, 64, true, true><<<(n + 63) / 64, 128>>>(h2, w2h, dinv, hl2, n);
    gather_agg<<<(n * 8 + T - 1) / T, T>>>(off, esrc, hl2, dinv, b2, h2, n);

    gemm_mma<64, 128, false, true><<<(n + 63) / 64, 128>>>(h2, wabh, nullptr, ab2, n);
    edge_mlp_csc<<<(n * 8 + T - 1) / T, T>>>(off, esrc, eidx, ab2, l1b, l2W, l2b, out, n);
}